// round 1
// baseline (speedup 1.0000x reference)
#include <cuda_runtime.h>
#include <cuda_bf16.h>
#include <cstdint>

// Problem constants
#define BATCH 256
#define CHAN  3
#define IMG   224
#define GSZ   32
#define NPATCH 3
#define DIMG  (NPATCH*CHAN*GSZ*GSZ)   // 9216
#define HG    1024
#define HL    1024
#define HOUT  2048                     // h_g + h_l
#define SPLITK1 8
#define KCHUNK1 (DIMG / SPLITK1)       // 1152

// ---------------- scratch (device globals: no allocation allowed) ----------------
__device__ float g_glimpse[BATCH * DIMG];                 // (256, 9216)
__device__ float g_A2[BATCH * (HG + HL)];                 // (256, 2048) = [g_out | l_out]
__device__ float g_part1[SPLITK1 * BATCH * HG];           // split-K partials GEMM1
__device__ float g_part2[2 * BATCH * HOUT];               // split partials GEMM2

// ---------------- foveate: glimpse extraction + avg pool ----------------
// One thread per output element of (b, k, ch, gy, gx) -> (256, 9216)
__global__ void foveate_kernel(const float* __restrict__ x,
                               const float* __restrict__ l,
                               float* __restrict__ glimpse) {
    int idx = blockIdx.x * blockDim.x + threadIdx.x;   // 0 .. 256*9216-1 exactly
    int gx = idx & 31;
    int gy = (idx >> 5) & 31;
    int v  = idx >> 10;            // b*9 + k*3 + ch
    int ch = v % 3;
    int k  = (v / 3) % 3;
    int b  = v / 9;

    float l0 = l[b * 2 + 0];       // col coordinate
    float l1 = l[b * 2 + 1];       // row coordinate
    // match JAX: (0.5 * ((l + 1.0) * h)).astype(int32) in f32, no FMA contraction
    int sc = (int)(__fmul_rn(0.5f, __fmul_rn(__fadd_rn(l0, 1.0f), 224.0f)));
    int sr = (int)(__fmul_rn(0.5f, __fmul_rn(__fadd_rn(l1, 1.0f), 224.0f)));

    int p   = 1 << k;              // pool factor 1,2,4
    int pad = (16 << k) + 1;       // size/2 + 1 = 17, 33, 65

    const float* xb = x + ((size_t)b * CHAN + ch) * IMG * IMG;
    int r0 = sr + gy * p - pad;
    int c0 = sc + gx * p - pad;

    float s = 0.0f;
    #pragma unroll 4
    for (int di = 0; di < p; di++) {
        int r = r0 + di;
        if (r < 0 || r >= IMG) continue;
        const float* row = xb + r * IMG;
        #pragma unroll 4
        for (int dj = 0; dj < p; dj++) {
            int c = c0 + dj;
            if (c >= 0 && c < IMG) s += row[c];
        }
    }
    glimpse[idx] = s * (1.0f / (float)(p * p));
}

// ---------------- l_out = relu(l_prev @ W2 + b2) -> right half of A2 ----------------
__global__ void lout_kernel(const float* __restrict__ l,
                            const float* __restrict__ W2,
                            const float* __restrict__ b2,
                            float* __restrict__ A2) {
    int idx = blockIdx.x * blockDim.x + threadIdx.x;   // 0 .. 256*1024-1
    int j = idx & (HL - 1);
    int b = idx >> 10;
    float s = fmaf(l[b * 2 + 0], W2[j], fmaf(l[b * 2 + 1], W2[HL + j], b2[j]));
    A2[(size_t)b * HOUT + HG + j] = fmaxf(s, 0.0f);
}

// ---------------- split-K tiled SGEMM: Cpart[z] = A[:, zk:(z+1)k] @ Bsel ----------------
// BM=BN=64, BK=16, 256 threads, 4x4 microtile per thread.
// Requires: M%64==0, N%64==0, kPerSplit%16==0, lda/ldb/k-offsets %4==0.
__global__ void sgemm64_kernel(const float* __restrict__ A, int lda,
                               const float* __restrict__ B0,
                               const float* __restrict__ B1,
                               int ldb,
                               float* __restrict__ Cpart,
                               int M, int N, int kPerSplit, int splitB1) {
    __shared__ float As[16][64];
    __shared__ float Bs[16][64];

    int z = blockIdx.z;
    const float* B = (z >= splitB1)
        ? (B1 + (size_t)(z - splitB1) * kPerSplit * ldb)
        : (B0 + (size_t)z * kPerSplit * ldb);
    const float* Ab = A + (size_t)z * kPerSplit;   // column offset into A

    int rowBase = blockIdx.y * 64;
    int colBase = blockIdx.x * 64;
    int tid = threadIdx.x;

    int aRow  = tid >> 2;          // 0..63
    int aCol4 = (tid & 3) * 4;     // 0,4,8,12
    int bRow  = tid >> 4;          // 0..15
    int bCol4 = (tid & 15) * 4;

    int ty = tid >> 4;             // 0..15
    int tx = tid & 15;             // 0..15

    float acc[4][4];
    #pragma unroll
    for (int i = 0; i < 4; i++)
        #pragma unroll
        for (int j = 0; j < 4; j++) acc[i][j] = 0.0f;

    for (int k0 = 0; k0 < kPerSplit; k0 += 16) {
        float4 av = *(const float4*)(Ab + (size_t)(rowBase + aRow) * lda + k0 + aCol4);
        As[aCol4 + 0][aRow] = av.x;
        As[aCol4 + 1][aRow] = av.y;
        As[aCol4 + 2][aRow] = av.z;
        As[aCol4 + 3][aRow] = av.w;
        *(float4*)&Bs[bRow][bCol4] =
            *(const float4*)(B + (size_t)(k0 + bRow) * ldb + colBase + bCol4);
        __syncthreads();

        #pragma unroll
        for (int kk = 0; kk < 16; kk++) {
            float4 a = *(const float4*)&As[kk][ty * 4];
            float4 bb = *(const float4*)&Bs[kk][tx * 4];
            float ar[4] = {a.x, a.y, a.z, a.w};
            float br[4] = {bb.x, bb.y, bb.z, bb.w};
            #pragma unroll
            for (int i = 0; i < 4; i++)
                #pragma unroll
                for (int j = 0; j < 4; j++)
                    acc[i][j] = fmaf(ar[i], br[j], acc[i][j]);
        }
        __syncthreads();
    }

    float* Cp = Cpart + (size_t)z * M * N;
    #pragma unroll
    for (int i = 0; i < 4; i++) {
        int r = rowBase + ty * 4 + i;
        #pragma unroll
        for (int j = 0; j < 4; j++) {
            Cp[(size_t)r * N + colBase + tx * 4 + j] = acc[i][j];
        }
    }
}

// ---------------- reduce split-K partials of GEMM1 + bias + relu -> A2 left half ----------------
__global__ void reduce1_kernel(const float* __restrict__ part,
                               const float* __restrict__ b1,
                               float* __restrict__ A2) {
    int idx = blockIdx.x * blockDim.x + threadIdx.x;   // 0 .. 256*1024-1
    int j = idx & (HG - 1);
    int b = idx >> 10;
    float s = b1[j];
    #pragma unroll
    for (int z = 0; z < SPLITK1; z++)
        s += part[(size_t)z * BATCH * HG + idx];
    A2[(size_t)b * HOUT + j] = fmaxf(s, 0.0f);
}

// ---------------- reduce GEMM2 partials + b3 + b4 + relu -> out ----------------
__global__ void reduce2_kernel(const float* __restrict__ part,
                               const float* __restrict__ b3,
                               const float* __restrict__ b4,
                               float* __restrict__ out) {
    int idx = blockIdx.x * blockDim.x + threadIdx.x;   // 0 .. 256*2048-1
    int j = idx & (HOUT - 1);
    float s = b3[j] + b4[j] + part[idx] + part[(size_t)BATCH * HOUT + idx];
    out[idx] = fmaxf(s, 0.0f);
}

// ---------------- launch ----------------
extern "C" void kernel_launch(void* const* d_in, const int* in_sizes, int n_in,
                              void* d_out, int out_size) {
    const float* x     = (const float*)d_in[0];
    const float* lprev = (const float*)d_in[1];
    const float* W1    = (const float*)d_in[2];
    const float* b1    = (const float*)d_in[3];
    const float* W2    = (const float*)d_in[4];
    const float* b2    = (const float*)d_in[5];
    const float* W3    = (const float*)d_in[6];
    const float* b3    = (const float*)d_in[7];
    const float* W4    = (const float*)d_in[8];
    const float* b4    = (const float*)d_in[9];
    float* out = (float*)d_out;

    float *glimpse, *A2, *part1, *part2;
    cudaGetSymbolAddress((void**)&glimpse, g_glimpse);
    cudaGetSymbolAddress((void**)&A2,      g_A2);
    cudaGetSymbolAddress((void**)&part1,   g_part1);
    cudaGetSymbolAddress((void**)&part2,   g_part2);

    // 1. foveate -> glimpse (256, 9216)
    foveate_kernel<<<(BATCH * DIMG) / 256, 256>>>(x, lprev, glimpse);

    // 2. l_out -> A2[:, 1024:2048]
    lout_kernel<<<(BATCH * HL) / 256, 256>>>(lprev, W2, b2, A2);

    // 3. GEMM1: glimpse(256x9216) @ W1(9216x1024), split-K=8
    sgemm64_kernel<<<dim3(HG / 64, BATCH / 64, SPLITK1), 256>>>(
        glimpse, DIMG, W1, W1, HG, part1, BATCH, HG, KCHUNK1, 1000);

    // 4. reduce + b1 + relu -> A2[:, 0:1024]
    reduce1_kernel<<<(BATCH * HG) / 256, 256>>>(part1, b1, A2);

    // 5. GEMM2: A2(256x2048) @ [W3; W4](2048x2048), split across W3/W4
    sgemm64_kernel<<<dim3(HOUT / 64, BATCH / 64, 2), 256>>>(
        A2, HOUT, W3, W4, HOUT, part2, BATCH, HOUT, HG, 1);

    // 6. reduce + b3 + b4 + relu -> out
    reduce2_kernel<<<(BATCH * HOUT) / 256, 256>>>(part2, b3, b4, out);
}

// round 7
// speedup vs baseline: 2.1618x; 2.1618x over previous
#include <cuda_runtime.h>
#include <cuda_bf16.h>
#include <cstdint>

// ---------------- problem constants ----------------
#define BATCH 256
#define CHAN  3
#define IMG   224
#define DIMG  9216          // K of GEMM1
#define HG    1024
#define HL    1024
#define HOUT  2048
#define SPLITK1 8
#define KCHUNK1 (DIMG / SPLITK1)   // 1152
#define SPLITK2 4
#define KCHUNK2 (HOUT / SPLITK2)   // 512

// ---------------- baseline-feature PTX helpers (sm_80+: valid on sm_103) ----------------
__device__ __forceinline__ uint32_t smem_to_u32(const void* p) {
    uint32_t a;
    asm("{ .reg .u64 t; cvta.to.shared.u64 t, %1; cvt.u32.u64 %0, t; }" : "=r"(a) : "l"(p));
    return a;
}
#define CP_ASYNC_16(dst, src) \
    asm volatile("cp.async.cg.shared.global [%0], [%1], 16;" :: "r"(dst), "l"(src))
#define CP_COMMIT asm volatile("cp.async.commit_group;" ::: "memory")
#define CP_WAIT(n) asm volatile("cp.async.wait_group %0;" :: "n"(n) : "memory")

__device__ __forceinline__ void ldsm_x4(uint32_t* r, uint32_t addr) {
    asm volatile("ldmatrix.sync.aligned.m8n8.x4.shared.b16 {%0,%1,%2,%3}, [%4];"
        : "=r"(r[0]), "=r"(r[1]), "=r"(r[2]), "=r"(r[3]) : "r"(addr));
}
__device__ __forceinline__ void mma_bf16(float* c, const uint32_t* a, const uint32_t* b) {
    asm volatile(
        "mma.sync.aligned.m16n8k16.row.col.f32.bf16.bf16.f32 "
        "{%0,%1,%2,%3}, {%4,%5,%6,%7}, {%8,%9}, {%0,%1,%2,%3};"
        : "+f"(c[0]), "+f"(c[1]), "+f"(c[2]), "+f"(c[3])
        : "r"(a[0]), "r"(a[1]), "r"(a[2]), "r"(a[3]), "r"(b[0]), "r"(b[1]));
}

// ---------------- scratch (device globals) ----------------
__device__ __align__(16) __nv_bfloat16 g_A1hi[BATCH * DIMG];
__device__ __align__(16) __nv_bfloat16 g_A1lo[BATCH * DIMG];
__device__ __align__(16) __nv_bfloat16 g_W1hi[HG * DIMG];     // (N=1024, K=9216)
__device__ __align__(16) __nv_bfloat16 g_W1lo[HG * DIMG];
__device__ __align__(16) __nv_bfloat16 g_B2hi[HOUT * HOUT];   // (N=2048, K=2048) = [W3;W4]^T
__device__ __align__(16) __nv_bfloat16 g_B2lo[HOUT * HOUT];
__device__ __align__(16) __nv_bfloat16 g_A2hi[BATCH * HOUT];
__device__ __align__(16) __nv_bfloat16 g_A2lo[BATCH * HOUT];
__device__ float g_part1[SPLITK1 * BATCH * HG];
__device__ float g_part2[SPLITK2 * BATCH * HOUT];

__device__ __forceinline__ void split_store(float v, __nv_bfloat16* hi_p, __nv_bfloat16* lo_p) {
    __nv_bfloat16 hi = __float2bfloat16(v);
    float r = v - __bfloat162float(hi);
    *hi_p = hi;
    *lo_p = __float2bfloat16(r);
}

// ---------------- foveate: glimpse extraction + pool, emit bf16 hi/lo ----------------
__global__ void foveate_kernel(const float* __restrict__ x,
                               const float* __restrict__ l,
                               __nv_bfloat16* __restrict__ ghi,
                               __nv_bfloat16* __restrict__ glo) {
    int idx = blockIdx.x * blockDim.x + threadIdx.x;   // 0 .. 256*9216-1
    int gx = idx & 31;
    int gy = (idx >> 5) & 31;
    int v  = idx >> 10;            // b*9 + k*3 + ch
    int ch = v % 3;
    int k  = (v / 3) % 3;
    int b  = v / 9;

    float l0 = l[b * 2 + 0];
    float l1 = l[b * 2 + 1];
    int sc = (int)(__fmul_rn(0.5f, __fmul_rn(__fadd_rn(l0, 1.0f), 224.0f)));
    int sr = (int)(__fmul_rn(0.5f, __fmul_rn(__fadd_rn(l1, 1.0f), 224.0f)));

    int p   = 1 << k;
    int pad = (16 << k) + 1;

    const float* xb = x + ((size_t)b * CHAN + ch) * IMG * IMG;
    int r0 = sr + gy * p - pad;
    int c0 = sc + gx * p - pad;

    float s = 0.0f;
    #pragma unroll 4
    for (int di = 0; di < p; di++) {
        int r = r0 + di;
        if (r < 0 || r >= IMG) continue;
        const float* row = xb + r * IMG;
        #pragma unroll 4
        for (int dj = 0; dj < p; dj++) {
            int c = c0 + dj;
            if (c >= 0 && c < IMG) s += row[c];
        }
    }
    s *= (1.0f / (float)(p * p));
    split_store(s, ghi + idx, glo + idx);
}

// ---------------- transpose + split W1 (9216,1024) -> (1024,9216) hi/lo ----------------
__global__ void conv_w1_kernel(const float* __restrict__ W,
                               __nv_bfloat16* __restrict__ Bh,
                               __nv_bfloat16* __restrict__ Bl) {
    __shared__ float s[32][33];
    int n0 = blockIdx.x * 32, k0 = blockIdx.y * 32;
    int tx = threadIdx.x, ty = threadIdx.y;   // 32 x 8
    #pragma unroll
    for (int i = 0; i < 32; i += 8)
        s[ty + i][tx] = W[(size_t)(k0 + ty + i) * HG + n0 + tx];
    __syncthreads();
    #pragma unroll
    for (int i = 0; i < 32; i += 8) {
        float v = s[tx][ty + i];   // = W[k0+tx][n0+ty+i]
        size_t o = (size_t)(n0 + ty + i) * DIMG + k0 + tx;
        split_store(v, Bh + o, Bl + o);
    }
}

// ---------------- transpose + split [W3;W4] (2048,2048) -> (2048,2048) hi/lo ----------------
__global__ void conv_b2_kernel(const float* __restrict__ W3,
                               const float* __restrict__ W4,
                               __nv_bfloat16* __restrict__ Bh,
                               __nv_bfloat16* __restrict__ Bl) {
    __shared__ float s[32][33];
    int n0 = blockIdx.x * 32, k0 = blockIdx.y * 32;
    int tx = threadIdx.x, ty = threadIdx.y;
    #pragma unroll
    for (int i = 0; i < 32; i += 8) {
        int k = k0 + ty + i;
        float v = (k < HG) ? W3[(size_t)k * HOUT + n0 + tx]
                           : W4[(size_t)(k - HG) * HOUT + n0 + tx];
        s[ty + i][tx] = v;
    }
    __syncthreads();
    #pragma unroll
    for (int i = 0; i < 32; i += 8) {
        float v = s[tx][ty + i];
        size_t o = (size_t)(n0 + ty + i) * HOUT + k0 + tx;
        split_store(v, Bh + o, Bl + o);
    }
}

// ---------------- l_out = relu(l @ W2 + b2) -> A2 cols [1024,2048), hi/lo ----------------
__global__ void lout_kernel(const float* __restrict__ l,
                            const float* __restrict__ W2,
                            const float* __restrict__ b2,
                            __nv_bfloat16* __restrict__ A2h,
                            __nv_bfloat16* __restrict__ A2l) {
    int idx = blockIdx.x * blockDim.x + threadIdx.x;   // 0 .. 256*1024-1
    int j = idx & (HL - 1);
    int b = idx >> 10;
    float s = fmaf(l[b * 2 + 0], W2[j], fmaf(l[b * 2 + 1], W2[HL + j], b2[j]));
    s = fmaxf(s, 0.0f);
    size_t o = (size_t)b * HOUT + HG + j;
    split_store(s, A2h + o, A2l + o);
}

// ---------------- HMMA split-precision GEMM ----------------
// CTA: 128x128 tile, BK=32, 8 warps (4 in M x 2 in N), double-buffered cp.async.
// A: (M, lda) K-major bf16 hi/lo.  B: (N, ldb) K-major bf16 hi/lo.
// C_partial[z] = Ahi*Bhi + Ahi*Blo + Alo*Bhi over K range [z*kPerSplit, ...)
#define AS_STRIDE_B 80                       // bytes per smem row (64B data + 16B pad)
#define TILE_B (128 * AS_STRIDE_B)           // 10240
#define SM_AHI 0
#define SM_ALO TILE_B
#define SM_BHI (2 * TILE_B)
#define SM_BLO (3 * TILE_B)
#define STAGE_B (4 * TILE_B)                 // 40960
#define GEMM_SMEM (2 * STAGE_B)              // 81920

__device__ __forceinline__ void cp_tile(uint32_t dst_base, const __nv_bfloat16* src,
                                        int row0, int ld, int kt, int tid) {
    #pragma unroll
    for (int i = 0; i < 2; i++) {
        int c = i * 256 + tid;            // 512 chunks of 16B
        int r = c >> 2, seg = c & 3;
        uint32_t dst = dst_base + r * AS_STRIDE_B + seg * 16;
        const void* s = src + (size_t)(row0 + r) * ld + kt + seg * 8;
        CP_ASYNC_16(dst, s);
    }
}

__global__ void __launch_bounds__(256)
hmma_gemm_kernel(const __nv_bfloat16* __restrict__ Ahi, const __nv_bfloat16* __restrict__ Alo, int lda,
                 const __nv_bfloat16* __restrict__ Bhi, const __nv_bfloat16* __restrict__ Blo, int ldb,
                 float* __restrict__ Cpart, int N, int kPerSplit) {
    extern __shared__ char smem[];
    uint32_t sb = smem_to_u32(smem);
    int tid = threadIdx.x, lane = tid & 31;
    int wid = tid >> 5;
    int wm = wid & 3;            // 4 warps in M: rows wm*32 .. wm*32+31
    int wn = wid >> 2;           // 2 warps in N: cols wn*64 .. wn*64+63

    int m0 = blockIdx.y * 128;
    int n0 = blockIdx.x * 128;
    int z  = blockIdx.z;
    int k0 = z * kPerSplit;
    int nt = kPerSplit >> 5;     // BK=32 steps

    float acc[2][8][4];
    #pragma unroll
    for (int a = 0; a < 2; a++)
        #pragma unroll
        for (int b = 0; b < 8; b++)
            #pragma unroll
            for (int c = 0; c < 4; c++) acc[a][b][c] = 0.0f;

    // prefetch stage 0
    {
        uint32_t base = sb;
        cp_tile(base + SM_AHI, Ahi, m0, lda, k0, tid);
        cp_tile(base + SM_ALO, Alo, m0, lda, k0, tid);
        cp_tile(base + SM_BHI, Bhi, n0, ldb, k0, tid);
        cp_tile(base + SM_BLO, Blo, n0, ldb, k0, tid);
        CP_COMMIT;
    }

    for (int t = 0; t < nt; t++) {
        if (t + 1 < nt) {
            uint32_t base = sb + ((t + 1) & 1) * STAGE_B;
            int kt = k0 + (t + 1) * 32;
            cp_tile(base + SM_AHI, Ahi, m0, lda, kt, tid);
            cp_tile(base + SM_ALO, Alo, m0, lda, kt, tid);
            cp_tile(base + SM_BHI, Bhi, n0, ldb, kt, tid);
            cp_tile(base + SM_BLO, Blo, n0, ldb, kt, tid);
            CP_COMMIT;
            CP_WAIT(1);
        } else {
            CP_WAIT(0);
        }
        __syncthreads();

        uint32_t base = sb + (t & 1) * STAGE_B;
        #pragma unroll
        for (int kk = 0; kk < 32; kk += 16) {
            uint32_t ah[2][4], al[2][4];
            #pragma unroll
            for (int mt = 0; mt < 2; mt++) {
                int row = wm * 32 + mt * 16 + (lane & 15);
                uint32_t off = row * AS_STRIDE_B + (kk + (lane >> 4) * 8) * 2;
                ldsm_x4(ah[mt], base + SM_AHI + off);
                ldsm_x4(al[mt], base + SM_ALO + off);
            }
            #pragma unroll
            for (int ng = 0; ng < 4; ng++) {
                uint32_t bh[4], bl[4];
                int nrow = wn * 64 + ng * 16 + ((lane >> 4) << 3) + (lane & 7);
                uint32_t off = nrow * AS_STRIDE_B + (kk + ((lane >> 3) & 1) * 8) * 2;
                ldsm_x4(bh, base + SM_BHI + off);
                ldsm_x4(bl, base + SM_BLO + off);
                #pragma unroll
                for (int mt = 0; mt < 2; mt++) {
                    #pragma unroll
                    for (int half = 0; half < 2; half++) {
                        float* c = acc[mt][ng * 2 + half];
                        mma_bf16(c, ah[mt], bh + half * 2);
                        mma_bf16(c, ah[mt], bl + half * 2);
                        mma_bf16(c, al[mt], bh + half * 2);
                    }
                }
            }
        }
        __syncthreads();
    }

    // epilogue: write fp32 partials
    float* C = Cpart + ((size_t)z * BATCH + m0) * N + n0;
    #pragma unroll
    for (int mt = 0; mt < 2; mt++) {
        int r0 = wm * 32 + mt * 16 + (lane >> 2);
        #pragma unroll
        for (int j = 0; j < 8; j++) {
            int col = wn * 64 + j * 8 + (lane & 3) * 2;
            float* c = acc[mt][j];
            *(float2*)(C + (size_t)r0 * N + col)       = make_float2(c[0], c[1]);
            *(float2*)(C + (size_t)(r0 + 8) * N + col) = make_float2(c[2], c[3]);
        }
    }
}

// ---------------- reduce GEMM1 partials + b1 + relu -> A2 cols [0,1024) hi/lo ----------------
__global__ void reduce1_kernel(const float* __restrict__ part,
                               const float* __restrict__ b1,
                               __nv_bfloat16* __restrict__ A2h,
                               __nv_bfloat16* __restrict__ A2l) {
    int idx = blockIdx.x * blockDim.x + threadIdx.x;   // 0 .. 256*1024-1
    int j = idx & (HG - 1);
    int b = idx >> 10;
    float s = b1[j];
    #pragma unroll
    for (int z = 0; z < SPLITK1; z++)
        s += part[(size_t)z * BATCH * HG + idx];
    s = fmaxf(s, 0.0f);
    size_t o = (size_t)b * HOUT + j;
    split_store(s, A2h + o, A2l + o);
}

// ---------------- reduce GEMM2 partials + b3 + b4 + relu -> out ----------------
__global__ void reduce2_kernel(const float* __restrict__ part,
                               const float* __restrict__ b3,
                               const float* __restrict__ b4,
                               float* __restrict__ out) {
    int idx = blockIdx.x * blockDim.x + threadIdx.x;   // 0 .. 256*2048-1
    int j = idx & (HOUT - 1);
    float s = b3[j] + b4[j];
    #pragma unroll
    for (int z = 0; z < SPLITK2; z++)
        s += part[(size_t)z * BATCH * HOUT + idx];
    out[idx] = fmaxf(s, 0.0f);
}

// ---------------- launch ----------------
extern "C" void kernel_launch(void* const* d_in, const int* in_sizes, int n_in,
                              void* d_out, int out_size) {
    const float* x     = (const float*)d_in[0];
    const float* lprev = (const float*)d_in[1];
    const float* W1    = (const float*)d_in[2];
    const float* b1    = (const float*)d_in[3];
    const float* W2    = (const float*)d_in[4];
    const float* b2    = (const float*)d_in[5];
    const float* W3    = (const float*)d_in[6];
    const float* b3    = (const float*)d_in[7];
    const float* W4    = (const float*)d_in[8];
    const float* b4    = (const float*)d_in[9];
    float* out = (float*)d_out;

    __nv_bfloat16 *A1h, *A1l, *W1h, *W1l, *B2h, *B2l, *A2h, *A2l;
    float *part1, *part2;
    cudaGetSymbolAddress((void**)&A1h, g_A1hi);
    cudaGetSymbolAddress((void**)&A1l, g_A1lo);
    cudaGetSymbolAddress((void**)&W1h, g_W1hi);
    cudaGetSymbolAddress((void**)&W1l, g_W1lo);
    cudaGetSymbolAddress((void**)&B2h, g_B2hi);
    cudaGetSymbolAddress((void**)&B2l, g_B2lo);
    cudaGetSymbolAddress((void**)&A2h, g_A2hi);
    cudaGetSymbolAddress((void**)&A2l, g_A2lo);
    cudaGetSymbolAddress((void**)&part1, g_part1);
    cudaGetSymbolAddress((void**)&part2, g_part2);

    cudaFuncSetAttribute(hmma_gemm_kernel,
                         cudaFuncAttributeMaxDynamicSharedMemorySize, GEMM_SMEM);

    // 1. foveate -> A1 hi/lo (256, 9216)
    foveate_kernel<<<(BATCH * DIMG) / 256, 256>>>(x, lprev, A1h, A1l);

    // 2. weight conversions (independent)
    conv_w1_kernel<<<dim3(HG / 32, DIMG / 32), dim3(32, 8)>>>(W1, W1h, W1l);
    conv_b2_kernel<<<dim3(HOUT / 32, HOUT / 32), dim3(32, 8)>>>(W3, W4, B2h, B2l);

    // 3. l_out -> A2[:, 1024:2048] hi/lo
    lout_kernel<<<(BATCH * HL) / 256, 256>>>(lprev, W2, b2, A2h, A2l);

    // 4. GEMM1: (256x9216) @ (9216x1024), split-K=8 -> 128 CTAs
    hmma_gemm_kernel<<<dim3(HG / 128, BATCH / 128, SPLITK1), 256, GEMM_SMEM>>>(
        A1h, A1l, DIMG, W1h, W1l, DIMG, part1, HG, KCHUNK1);

    // 5. reduce + b1 + relu -> A2[:, 0:1024] hi/lo
    reduce1_kernel<<<(BATCH * HG) / 256, 256>>>(part1, b1, A2h, A2l);

    // 6. GEMM2: (256x2048) @ (2048x2048), split-K=4 -> 128 CTAs
    hmma_gemm_kernel<<<dim3(HOUT / 128, BATCH / 128, SPLITK2), 256, GEMM_SMEM>>>(
        A2h, A2l, HOUT, B2h, B2l, HOUT, part2, HOUT, KCHUNK2);

    // 7. reduce + b3 + b4 + relu -> out
    reduce2_kernel<<<(BATCH * HOUT) / 256, 256>>>(part2, b3, b4, out);
}

// round 10
// speedup vs baseline: 2.4027x; 1.1114x over previous
#include <cuda_runtime.h>
#include <cuda_bf16.h>
#include <cstdint>

// ---------------- problem constants ----------------
#define BATCH 256
#define CHAN  3
#define IMG   224
#define DIMG  9216          // K of GEMM1
#define HG    1024
#define HL    1024
#define HOUT  2048
#define SPLITK1 18
#define KCHUNK1 (DIMG / SPLITK1)   // 512
#define SPLITK2 8
#define KCHUNK2 (HOUT / SPLITK2)   // 256

// ---------------- baseline-feature PTX helpers (sm_80+: valid on sm_103) ----------------
__device__ __forceinline__ uint32_t smem_to_u32(const void* p) {
    uint32_t a;
    asm("{ .reg .u64 t; cvta.to.shared.u64 t, %1; cvt.u32.u64 %0, t; }" : "=r"(a) : "l"(p));
    return a;
}
#define CP_ASYNC_16(dst, src) \
    asm volatile("cp.async.cg.shared.global [%0], [%1], 16;" :: "r"(dst), "l"(src))
#define CP_COMMIT asm volatile("cp.async.commit_group;" ::: "memory")
#define CP_WAIT(n) asm volatile("cp.async.wait_group %0;" :: "n"(n) : "memory")

__device__ __forceinline__ void ldsm_x4(uint32_t* r, uint32_t addr) {
    asm volatile("ldmatrix.sync.aligned.m8n8.x4.shared.b16 {%0,%1,%2,%3}, [%4];"
        : "=r"(r[0]), "=r"(r[1]), "=r"(r[2]), "=r"(r[3]) : "r"(addr));
}
__device__ __forceinline__ void mma_bf16(float* c, const uint32_t* a, const uint32_t* b) {
    asm volatile(
        "mma.sync.aligned.m16n8k16.row.col.f32.bf16.bf16.f32 "
        "{%0,%1,%2,%3}, {%4,%5,%6,%7}, {%8,%9}, {%0,%1,%2,%3};"
        : "+f"(c[0]), "+f"(c[1]), "+f"(c[2]), "+f"(c[3])
        : "r"(a[0]), "r"(a[1]), "r"(a[2]), "r"(a[3]), "r"(b[0]), "r"(b[1]));
}

// ---------------- scratch (device globals) ----------------
__device__ __align__(16) __nv_bfloat16 g_A1hi[BATCH * DIMG];
__device__ __align__(16) __nv_bfloat16 g_A1lo[BATCH * DIMG];
__device__ __align__(16) __nv_bfloat16 g_W1hi[HG * DIMG];     // (N=1024, K=9216)
__device__ __align__(16) __nv_bfloat16 g_W1lo[HG * DIMG];
__device__ __align__(16) __nv_bfloat16 g_B2hi[HOUT * HOUT];   // (N=2048, K=2048) = [W3;W4]^T
__device__ __align__(16) __nv_bfloat16 g_B2lo[HOUT * HOUT];
__device__ __align__(16) __nv_bfloat16 g_A2hi[BATCH * HOUT];
__device__ __align__(16) __nv_bfloat16 g_A2lo[BATCH * HOUT];
__device__ float g_part1[SPLITK1 * BATCH * HG];
__device__ float g_part2[SPLITK2 * BATCH * HOUT];

__device__ __forceinline__ void split_store(float v, __nv_bfloat16* hi_p, __nv_bfloat16* lo_p) {
    __nv_bfloat16 hi = __float2bfloat16(v);
    float r = v - __bfloat162float(hi);
    *hi_p = hi;
    *lo_p = __float2bfloat16(r);
}

// ---------------- foveate: glimpse extraction + pool, emit bf16 hi/lo ----------------
__global__ void foveate_kernel(const float* __restrict__ x,
                               const float* __restrict__ l,
                               __nv_bfloat16* __restrict__ ghi,
                               __nv_bfloat16* __restrict__ glo) {
    int idx = blockIdx.x * blockDim.x + threadIdx.x;   // 0 .. 256*9216-1
    int gx = idx & 31;
    int gy = (idx >> 5) & 31;
    int v  = idx >> 10;            // b*9 + k*3 + ch
    int ch = v % 3;
    int k  = (v / 3) % 3;
    int b  = v / 9;

    float l0 = l[b * 2 + 0];
    float l1 = l[b * 2 + 1];
    int sc = (int)(__fmul_rn(0.5f, __fmul_rn(__fadd_rn(l0, 1.0f), 224.0f)));
    int sr = (int)(__fmul_rn(0.5f, __fmul_rn(__fadd_rn(l1, 1.0f), 224.0f)));

    int p   = 1 << k;
    int pad = (16 << k) + 1;

    const float* xb = x + ((size_t)b * CHAN + ch) * IMG * IMG;
    int r0 = sr + gy * p - pad;
    int c0 = sc + gx * p - pad;

    float s = 0.0f;
    #pragma unroll 4
    for (int di = 0; di < p; di++) {
        int r = r0 + di;
        if (r < 0 || r >= IMG) continue;
        const float* row = xb + r * IMG;
        #pragma unroll 4
        for (int dj = 0; dj < p; dj++) {
            int c = c0 + dj;
            if (c >= 0 && c < IMG) s += row[c];
        }
    }
    s *= (1.0f / (float)(p * p));
    split_store(s, ghi + idx, glo + idx);
}

// ---------------- transpose + split W1 (9216,1024) -> (1024,9216) hi/lo ----------------
__global__ void conv_w1_kernel(const float* __restrict__ W,
                               __nv_bfloat16* __restrict__ Bh,
                               __nv_bfloat16* __restrict__ Bl) {
    __shared__ float s[32][33];
    int n0 = blockIdx.x * 32, k0 = blockIdx.y * 32;
    int tx = threadIdx.x, ty = threadIdx.y;   // 32 x 8
    #pragma unroll
    for (int i = 0; i < 32; i += 8)
        s[ty + i][tx] = W[(size_t)(k0 + ty + i) * HG + n0 + tx];
    __syncthreads();
    #pragma unroll
    for (int i = 0; i < 32; i += 8) {
        float v = s[tx][ty + i];   // = W[k0+tx][n0+ty+i]
        size_t o = (size_t)(n0 + ty + i) * DIMG + k0 + tx;
        split_store(v, Bh + o, Bl + o);
    }
}

// ---------------- transpose + split [W3;W4] (2048,2048) -> (2048,2048) hi/lo ----------------
__global__ void conv_b2_kernel(const float* __restrict__ W3,
                               const float* __restrict__ W4,
                               __nv_bfloat16* __restrict__ Bh,
                               __nv_bfloat16* __restrict__ Bl) {
    __shared__ float s[32][33];
    int n0 = blockIdx.x * 32, k0 = blockIdx.y * 32;
    int tx = threadIdx.x, ty = threadIdx.y;
    #pragma unroll
    for (int i = 0; i < 32; i += 8) {
        int k = k0 + ty + i;
        float v = (k < HG) ? W3[(size_t)k * HOUT + n0 + tx]
                           : W4[(size_t)(k - HG) * HOUT + n0 + tx];
        s[ty + i][tx] = v;
    }
    __syncthreads();
    #pragma unroll
    for (int i = 0; i < 32; i += 8) {
        float v = s[tx][ty + i];
        size_t o = (size_t)(n0 + ty + i) * HOUT + k0 + tx;
        split_store(v, Bh + o, Bl + o);
    }
}

// ---------------- HMMA split-precision GEMM ----------------
// CTA: 256x128 tile, BK=32, 8 warps (4 in M x 2 in N), warp tile 64x64,
// double-buffered cp.async. A: (M, lda) K-major bf16 hi/lo. B: (N, ldb) K-major.
// C_partial[z] = Ahi*Bhi + Ahi*Blo + Alo*Bhi over K range [z*kPerSplit, ...)
#define AS_STRIDE_B 80                       // bytes per smem row (64B data + 16B pad)
#define A_TILE_B (256 * AS_STRIDE_B)         // 20480
#define B_TILE_B (128 * AS_STRIDE_B)         // 10240
#define SM_AHI 0
#define SM_ALO A_TILE_B
#define SM_BHI (2 * A_TILE_B)
#define SM_BLO (2 * A_TILE_B + B_TILE_B)
#define STAGE_B (2 * A_TILE_B + 2 * B_TILE_B)   // 61440
#define GEMM_SMEM (2 * STAGE_B)                  // 122880

template<int NROWS>
__device__ __forceinline__ void cp_tile(uint32_t dst_base, const __nv_bfloat16* src,
                                        int row0, int ld, int kt, int tid) {
    #pragma unroll
    for (int i = 0; i < NROWS / 64; i++) {
        int c = i * 256 + tid;            // NROWS*4 chunks of 16B
        int r = c >> 2, seg = c & 3;
        uint32_t dst = dst_base + r * AS_STRIDE_B + seg * 16;
        const void* s = src + (size_t)(row0 + r) * ld + kt + seg * 8;
        CP_ASYNC_16(dst, s);
    }
}

__global__ void __launch_bounds__(256)
hmma_gemm_kernel(const __nv_bfloat16* __restrict__ Ahi, const __nv_bfloat16* __restrict__ Alo, int lda,
                 const __nv_bfloat16* __restrict__ Bhi, const __nv_bfloat16* __restrict__ Blo, int ldb,
                 float* __restrict__ Cpart, int N, int kPerSplit) {
    extern __shared__ char smem[];
    uint32_t sb = smem_to_u32(smem);
    int tid = threadIdx.x, lane = tid & 31;
    int wid = tid >> 5;
    int wm = wid & 3;            // 4 warps in M: rows wm*64 .. wm*64+63
    int wn = wid >> 2;           // 2 warps in N: cols wn*64 .. wn*64+63

    int m0 = blockIdx.y * 256;
    int n0 = blockIdx.x * 128;
    int z  = blockIdx.z;
    int k0 = z * kPerSplit;
    int nt = kPerSplit >> 5;     // BK=32 steps

    float acc[4][8][4];
    #pragma unroll
    for (int a = 0; a < 4; a++)
        #pragma unroll
        for (int b = 0; b < 8; b++)
            #pragma unroll
            for (int c = 0; c < 4; c++) acc[a][b][c] = 0.0f;

    // prefetch stage 0
    {
        uint32_t base = sb;
        cp_tile<256>(base + SM_AHI, Ahi, m0, lda, k0, tid);
        cp_tile<256>(base + SM_ALO, Alo, m0, lda, k0, tid);
        cp_tile<128>(base + SM_BHI, Bhi, n0, ldb, k0, tid);
        cp_tile<128>(base + SM_BLO, Blo, n0, ldb, k0, tid);
        CP_COMMIT;
    }

    for (int t = 0; t < nt; t++) {
        if (t + 1 < nt) {
            uint32_t base = sb + ((t + 1) & 1) * STAGE_B;
            int kt = k0 + (t + 1) * 32;
            cp_tile<256>(base + SM_AHI, Ahi, m0, lda, kt, tid);
            cp_tile<256>(base + SM_ALO, Alo, m0, lda, kt, tid);
            cp_tile<128>(base + SM_BHI, Bhi, n0, ldb, kt, tid);
            cp_tile<128>(base + SM_BLO, Blo, n0, ldb, kt, tid);
            CP_COMMIT;
            CP_WAIT(1);
        } else {
            CP_WAIT(0);
        }
        __syncthreads();

        uint32_t base = sb + (t & 1) * STAGE_B;
        #pragma unroll
        for (int kk = 0; kk < 32; kk += 16) {
            uint32_t ah[4][4], al[4][4];
            #pragma unroll
            for (int mt = 0; mt < 4; mt++) {
                int row = wm * 64 + mt * 16 + (lane & 15);
                uint32_t off = row * AS_STRIDE_B + (kk + (lane >> 4) * 8) * 2;
                ldsm_x4(ah[mt], base + SM_AHI + off);
                ldsm_x4(al[mt], base + SM_ALO + off);
            }
            #pragma unroll
            for (int ng = 0; ng < 4; ng++) {
                uint32_t bh[4], bl[4];
                int nrow = wn * 64 + ng * 16 + ((lane >> 4) << 3) + (lane & 7);
                uint32_t off = nrow * AS_STRIDE_B + (kk + ((lane >> 3) & 1) * 8) * 2;
                ldsm_x4(bh, base + SM_BHI + off);
                ldsm_x4(bl, base + SM_BLO + off);
                #pragma unroll
                for (int mt = 0; mt < 4; mt++) {
                    #pragma unroll
                    for (int half = 0; half < 2; half++) {
                        float* c = acc[mt][ng * 2 + half];
                        mma_bf16(c, ah[mt], bh + half * 2);
                        mma_bf16(c, ah[mt], bl + half * 2);
                        mma_bf16(c, al[mt], bh + half * 2);
                    }
                }
            }
        }
        __syncthreads();
    }

    // epilogue: write fp32 partials
    float* C = Cpart + ((size_t)z * BATCH + m0) * N + n0;
    #pragma unroll
    for (int mt = 0; mt < 4; mt++) {
        int r0 = wm * 64 + mt * 16 + (lane >> 2);
        #pragma unroll
        for (int j = 0; j < 8; j++) {
            int col = wn * 64 + j * 8 + (lane & 3) * 2;
            float* c = acc[mt][j];
            *(float2*)(C + (size_t)r0 * N + col)       = make_float2(c[0], c[1]);
            *(float2*)(C + (size_t)(r0 + 8) * N + col) = make_float2(c[2], c[3]);
        }
    }
}

// ---------------- fused: reduce GEMM1 partials + b1 + relu -> A2[:,0:1024)
//                  AND l_out = relu(l @ W2 + b2) -> A2[:,1024:2048), both hi/lo ----------------
__global__ void reduce1_lout_kernel(const float* __restrict__ part,
                                    const float* __restrict__ b1,
                                    const float* __restrict__ l,
                                    const float* __restrict__ W2,
                                    const float* __restrict__ b2,
                                    __nv_bfloat16* __restrict__ A2h,
                                    __nv_bfloat16* __restrict__ A2l) {
    int idx = blockIdx.x * blockDim.x + threadIdx.x;   // 0 .. 256*2048-1
    int j = idx & (HOUT - 1);
    int b = idx >> 11;
    float s;
    if (j < HG) {
        s = b1[j];
        int pidx = b * HG + j;
        #pragma unroll
        for (int z = 0; z < SPLITK1; z++)
            s += part[(size_t)z * BATCH * HG + pidx];
    } else {
        int jl = j - HG;
        s = fmaf(l[b * 2 + 0], W2[jl], fmaf(l[b * 2 + 1], W2[HL + jl], b2[jl]));
    }
    s = fmaxf(s, 0.0f);
    split_store(s, A2h + idx, A2l + idx);
}

// ---------------- reduce GEMM2 partials + b3 + b4 + relu -> out ----------------
__global__ void reduce2_kernel(const float* __restrict__ part,
                               const float* __restrict__ b3,
                               const float* __restrict__ b4,
                               float* __restrict__ out) {
    int idx = blockIdx.x * blockDim.x + threadIdx.x;   // 0 .. 256*2048-1
    int j = idx & (HOUT - 1);
    float s = b3[j] + b4[j];
    #pragma unroll
    for (int z = 0; z < SPLITK2; z++)
        s += part[(size_t)z * BATCH * HOUT + idx];
    out[idx] = fmaxf(s, 0.0f);
}

// ---------------- launch ----------------
extern "C" void kernel_launch(void* const* d_in, const int* in_sizes, int n_in,
                              void* d_out, int out_size) {
    const float* x     = (const float*)d_in[0];
    const float* lprev = (const float*)d_in[1];
    const float* W1    = (const float*)d_in[2];
    const float* b1    = (const float*)d_in[3];
    const float* W2    = (const float*)d_in[4];
    const float* b2    = (const float*)d_in[5];
    const float* W3    = (const float*)d_in[6];
    const float* b3    = (const float*)d_in[7];
    const float* W4    = (const float*)d_in[8];
    const float* b4    = (const float*)d_in[9];
    float* out = (float*)d_out;

    __nv_bfloat16 *A1h, *A1l, *W1h, *W1l, *B2h, *B2l, *A2h, *A2l;
    float *part1, *part2;
    cudaGetSymbolAddress((void**)&A1h, g_A1hi);
    cudaGetSymbolAddress((void**)&A1l, g_A1lo);
    cudaGetSymbolAddress((void**)&W1h, g_W1hi);
    cudaGetSymbolAddress((void**)&W1l, g_W1lo);
    cudaGetSymbolAddress((void**)&B2h, g_B2hi);
    cudaGetSymbolAddress((void**)&B2l, g_B2lo);
    cudaGetSymbolAddress((void**)&A2h, g_A2hi);
    cudaGetSymbolAddress((void**)&A2l, g_A2lo);
    cudaGetSymbolAddress((void**)&part1, g_part1);
    cudaGetSymbolAddress((void**)&part2, g_part2);

    cudaFuncSetAttribute(hmma_gemm_kernel,
                         cudaFuncAttributeMaxDynamicSharedMemorySize, GEMM_SMEM);

    // 1. foveate -> A1 hi/lo (256, 9216)
    foveate_kernel<<<(BATCH * DIMG) / 256, 256>>>(x, lprev, A1h, A1l);

    // 2. weight conversions (independent)
    conv_w1_kernel<<<dim3(HG / 32, DIMG / 32), dim3(32, 8)>>>(W1, W1h, W1l);
    conv_b2_kernel<<<dim3(HOUT / 32, HOUT / 32), dim3(32, 8)>>>(W3, W4, B2h, B2l);

    // 3. GEMM1: (256x9216) @ (9216x1024), split-K=18 -> 144 CTAs
    hmma_gemm_kernel<<<dim3(HG / 128, BATCH / 256, SPLITK1), 256, GEMM_SMEM>>>(
        A1h, A1l, DIMG, W1h, W1l, DIMG, part1, HG, KCHUNK1);

    // 4. fused reduce + b1 + relu (left) and l_out (right) -> A2 hi/lo
    reduce1_lout_kernel<<<(BATCH * HOUT) / 256, 256>>>(part1, b1, lprev, W2, b2, A2h, A2l);

    // 5. GEMM2: (256x2048) @ (2048x2048), split-K=8 -> 128 CTAs
    hmma_gemm_kernel<<<dim3(HOUT / 128, BATCH / 256, SPLITK2), 256, GEMM_SMEM>>>(
        A2h, A2l, HOUT, B2h, B2l, HOUT, part2, HOUT, KCHUNK2);

    // 6. reduce + b3 + b4 + relu -> out
    reduce2_kernel<<<(BATCH * HOUT) / 256, 256>>>(part2, b3, b4, out);
}

// round 13
// speedup vs baseline: 2.4108x; 1.0034x over previous
#include <cuda_runtime.h>
#include <cuda_bf16.h>
#include <cstdint>

// ---------------- problem constants ----------------
#define BATCH 256
#define CHAN  3
#define IMG   224
#define DIMG  9216          // K of GEMM1
#define HG    1024
#define HL    1024
#define HOUT  2048
#define SPLITK1 18
#define KCHUNK1 (DIMG / SPLITK1)   // 512
#define SPLITK2 8
#define KCHUNK2 (HOUT / SPLITK2)   // 256

// ---------------- baseline-feature PTX helpers (sm_80+: valid on sm_103) ----------------
__device__ __forceinline__ uint32_t smem_to_u32(const void* p) {
    uint32_t a;
    asm("{ .reg .u64 t; cvta.to.shared.u64 t, %1; cvt.u32.u64 %0, t; }" : "=r"(a) : "l"(p));
    return a;
}
#define CP_ASYNC_16(dst, src) \
    asm volatile("cp.async.cg.shared.global [%0], [%1], 16;" :: "r"(dst), "l"(src))
#define CP_COMMIT asm volatile("cp.async.commit_group;" ::: "memory")
#define CP_WAIT(n) asm volatile("cp.async.wait_group %0;" :: "n"(n) : "memory")

__device__ __forceinline__ void ldsm_x4(uint32_t* r, uint32_t addr) {
    asm volatile("ldmatrix.sync.aligned.m8n8.x4.shared.b16 {%0,%1,%2,%3}, [%4];"
        : "=r"(r[0]), "=r"(r[1]), "=r"(r[2]), "=r"(r[3]) : "r"(addr));
}
__device__ __forceinline__ void mma_bf16(float* c, const uint32_t* a, const uint32_t* b) {
    asm volatile(
        "mma.sync.aligned.m16n8k16.row.col.f32.bf16.bf16.f32 "
        "{%0,%1,%2,%3}, {%4,%5,%6,%7}, {%8,%9}, {%0,%1,%2,%3};"
        : "+f"(c[0]), "+f"(c[1]), "+f"(c[2]), "+f"(c[3])
        : "r"(a[0]), "r"(a[1]), "r"(a[2]), "r"(a[3]), "r"(b[0]), "r"(b[1]));
}

// ---------------- scratch (device globals) ----------------
__device__ __align__(16) __nv_bfloat16 g_A1hi[BATCH * DIMG];
__device__ __align__(16) __nv_bfloat16 g_A1lo[BATCH * DIMG];
__device__ __align__(16) __nv_bfloat16 g_W1hi[HG * DIMG];     // (N=1024, K=9216)
__device__ __align__(16) __nv_bfloat16 g_W1lo[HG * DIMG];
__device__ __align__(16) __nv_bfloat16 g_B2hi[HOUT * HOUT];   // (N=2048, K=2048) = [W3;W4]^T
__device__ __align__(16) __nv_bfloat16 g_B2lo[HOUT * HOUT];
__device__ __align__(16) __nv_bfloat16 g_A2hi[BATCH * HOUT];
__device__ __align__(16) __nv_bfloat16 g_A2lo[BATCH * HOUT];
__device__ float g_part1[SPLITK1 * BATCH * HG];
__device__ float g_part2[SPLITK2 * BATCH * HOUT];

__device__ __forceinline__ void split_store(float v, __nv_bfloat16* hi_p, __nv_bfloat16* lo_p) {
    __nv_bfloat16 hi = __float2bfloat16(v);
    float r = v - __bfloat162float(hi);
    *hi_p = hi;
    *lo_p = __float2bfloat16(r);
}

// ---------------- foveate: glimpse extraction + pool, emit bf16 hi/lo ----------------
__global__ void foveate_kernel(const float* __restrict__ x,
                               const float* __restrict__ l,
                               __nv_bfloat16* __restrict__ ghi,
                               __nv_bfloat16* __restrict__ glo) {
    int idx = blockIdx.x * blockDim.x + threadIdx.x;   // 0 .. 256*9216-1
    int gx = idx & 31;
    int gy = (idx >> 5) & 31;
    int v  = idx >> 10;            // b*9 + k*3 + ch
    int ch = v % 3;
    int k  = (v / 3) % 3;
    int b  = v / 9;

    float l0 = l[b * 2 + 0];
    float l1 = l[b * 2 + 1];
    int sc = (int)(__fmul_rn(0.5f, __fmul_rn(__fadd_rn(l0, 1.0f), 224.0f)));
    int sr = (int)(__fmul_rn(0.5f, __fmul_rn(__fadd_rn(l1, 1.0f), 224.0f)));

    int p   = 1 << k;
    int pad = (16 << k) + 1;

    const float* xb = x + ((size_t)b * CHAN + ch) * IMG * IMG;
    int r0 = sr + gy * p - pad;
    int c0 = sc + gx * p - pad;

    float s = 0.0f;
    #pragma unroll 4
    for (int di = 0; di < p; di++) {
        int r = r0 + di;
        if (r < 0 || r >= IMG) continue;
        const float* row = xb + r * IMG;
        #pragma unroll 4
        for (int dj = 0; dj < p; dj++) {
            int c = c0 + dj;
            if (c >= 0 && c < IMG) s += row[c];
        }
    }
    s *= (1.0f / (float)(p * p));
    split_store(s, ghi + idx, glo + idx);
}

// ---------------- transpose + split W1 (9216,1024) -> (1024,9216) hi/lo ----------------
__global__ void conv_w1_kernel(const float* __restrict__ W,
                               __nv_bfloat16* __restrict__ Bh,
                               __nv_bfloat16* __restrict__ Bl) {
    __shared__ float s[32][33];
    int n0 = blockIdx.x * 32, k0 = blockIdx.y * 32;
    int tx = threadIdx.x, ty = threadIdx.y;   // 32 x 8
    #pragma unroll
    for (int i = 0; i < 32; i += 8)
        s[ty + i][tx] = W[(size_t)(k0 + ty + i) * HG + n0 + tx];
    __syncthreads();
    #pragma unroll
    for (int i = 0; i < 32; i += 8) {
        float v = s[tx][ty + i];   // = W[k0+tx][n0+ty+i]
        size_t o = (size_t)(n0 + ty + i) * DIMG + k0 + tx;
        split_store(v, Bh + o, Bl + o);
    }
}

// ---------------- transpose + split [W3;W4] (2048,2048) -> (2048,2048) hi/lo ----------------
__global__ void conv_b2_kernel(const float* __restrict__ W3,
                               const float* __restrict__ W4,
                               __nv_bfloat16* __restrict__ Bh,
                               __nv_bfloat16* __restrict__ Bl) {
    __shared__ float s[32][33];
    int n0 = blockIdx.x * 32, k0 = blockIdx.y * 32;
    int tx = threadIdx.x, ty = threadIdx.y;
    #pragma unroll
    for (int i = 0; i < 32; i += 8) {
        int k = k0 + ty + i;
        float v = (k < HG) ? W3[(size_t)k * HOUT + n0 + tx]
                           : W4[(size_t)(k - HG) * HOUT + n0 + tx];
        s[ty + i][tx] = v;
    }
    __syncthreads();
    #pragma unroll
    for (int i = 0; i < 32; i += 8) {
        float v = s[tx][ty + i];
        size_t o = (size_t)(n0 + ty + i) * HOUT + k0 + tx;
        split_store(v, Bh + o, Bl + o);
    }
}

// ---------------- HMMA split-precision GEMM ----------------
// CTA: 128x128 tile, BK=32, 4 warps (2 in M x 2 in N), warp tile 64x64,
// double-buffered cp.async, 2 CTAs/SM. A: (M, lda) K-major bf16 hi/lo. B: (N, ldb).
// C_partial[z] = Ahi*Bhi + Ahi*Blo + Alo*Bhi over K range [z*kPerSplit, ...)
#define AS_STRIDE_B 80                       // bytes per smem row (64B data + 16B pad)
#define TILE_B (128 * AS_STRIDE_B)           // 10240
#define SM_AHI 0
#define SM_ALO TILE_B
#define SM_BHI (2 * TILE_B)
#define SM_BLO (3 * TILE_B)
#define STAGE_B (4 * TILE_B)                 // 40960
#define GEMM_SMEM (2 * STAGE_B)              // 81920

// 128 rows x 64B, 128 threads: 512 chunks of 16B -> 4 per thread
__device__ __forceinline__ void cp_tile128(uint32_t dst_base, const __nv_bfloat16* src,
                                           int row0, int ld, int kt, int tid) {
    #pragma unroll
    for (int i = 0; i < 4; i++) {
        int c = i * 128 + tid;
        int r = c >> 2, seg = c & 3;
        uint32_t dst = dst_base + r * AS_STRIDE_B + seg * 16;
        const void* s = src + (size_t)(row0 + r) * ld + kt + seg * 8;
        CP_ASYNC_16(dst, s);
    }
}

__global__ void __launch_bounds__(128, 2)
hmma_gemm_kernel(const __nv_bfloat16* __restrict__ Ahi, const __nv_bfloat16* __restrict__ Alo, int lda,
                 const __nv_bfloat16* __restrict__ Bhi, const __nv_bfloat16* __restrict__ Blo, int ldb,
                 float* __restrict__ Cpart, int N, int kPerSplit) {
    extern __shared__ char smem[];
    uint32_t sb = smem_to_u32(smem);
    int tid = threadIdx.x, lane = tid & 31;
    int wid = tid >> 5;
    int wm = wid & 1;            // 2 warps in M: rows wm*64 .. wm*64+63
    int wn = wid >> 1;           // 2 warps in N: cols wn*64 .. wn*64+63

    int m0 = blockIdx.y * 128;
    int n0 = blockIdx.x * 128;
    int z  = blockIdx.z;
    int k0 = z * kPerSplit;
    int nt = kPerSplit >> 5;     // BK=32 steps

    float acc[4][8][4];
    #pragma unroll
    for (int a = 0; a < 4; a++)
        #pragma unroll
        for (int b = 0; b < 8; b++)
            #pragma unroll
            for (int c = 0; c < 4; c++) acc[a][b][c] = 0.0f;

    // prefetch stage 0
    {
        uint32_t base = sb;
        cp_tile128(base + SM_AHI, Ahi, m0, lda, k0, tid);
        cp_tile128(base + SM_ALO, Alo, m0, lda, k0, tid);
        cp_tile128(base + SM_BHI, Bhi, n0, ldb, k0, tid);
        cp_tile128(base + SM_BLO, Blo, n0, ldb, k0, tid);
        CP_COMMIT;
    }

    for (int t = 0; t < nt; t++) {
        if (t + 1 < nt) {
            uint32_t base = sb + ((t + 1) & 1) * STAGE_B;
            int kt = k0 + (t + 1) * 32;
            cp_tile128(base + SM_AHI, Ahi, m0, lda, kt, tid);
            cp_tile128(base + SM_ALO, Alo, m0, lda, kt, tid);
            cp_tile128(base + SM_BHI, Bhi, n0, ldb, kt, tid);
            cp_tile128(base + SM_BLO, Blo, n0, ldb, kt, tid);
            CP_COMMIT;
            CP_WAIT(1);
        } else {
            CP_WAIT(0);
        }
        __syncthreads();

        uint32_t base = sb + (t & 1) * STAGE_B;
        #pragma unroll
        for (int kk = 0; kk < 32; kk += 16) {
            uint32_t ah[4][4], al[4][4];
            #pragma unroll
            for (int mt = 0; mt < 4; mt++) {
                int row = wm * 64 + mt * 16 + (lane & 15);
                uint32_t off = row * AS_STRIDE_B + (kk + (lane >> 4) * 8) * 2;
                ldsm_x4(ah[mt], base + SM_AHI + off);
                ldsm_x4(al[mt], base + SM_ALO + off);
            }
            #pragma unroll
            for (int ng = 0; ng < 4; ng++) {
                uint32_t bh[4], bl[4];
                int nrow = wn * 64 + ng * 16 + ((lane >> 4) << 3) + (lane & 7);
                uint32_t off = nrow * AS_STRIDE_B + (kk + ((lane >> 3) & 1) * 8) * 2;
                ldsm_x4(bh, base + SM_BHI + off);
                ldsm_x4(bl, base + SM_BLO + off);
                #pragma unroll
                for (int mt = 0; mt < 4; mt++) {
                    #pragma unroll
                    for (int half = 0; half < 2; half++) {
                        float* c = acc[mt][ng * 2 + half];
                        mma_bf16(c, ah[mt], bh + half * 2);
                        mma_bf16(c, ah[mt], bl + half * 2);
                        mma_bf16(c, al[mt], bh + half * 2);
                    }
                }
            }
        }
        __syncthreads();
    }

    // epilogue: write fp32 partials
    float* C = Cpart + ((size_t)z * BATCH + m0) * N + n0;
    #pragma unroll
    for (int mt = 0; mt < 4; mt++) {
        int r0 = wm * 64 + mt * 16 + (lane >> 2);
        #pragma unroll
        for (int j = 0; j < 8; j++) {
            int col = wn * 64 + j * 8 + (lane & 3) * 2;
            float* c = acc[mt][j];
            *(float2*)(C + (size_t)r0 * N + col)       = make_float2(c[0], c[1]);
            *(float2*)(C + (size_t)(r0 + 8) * N + col) = make_float2(c[2], c[3]);
        }
    }
}

// ---------------- fused: reduce GEMM1 partials + b1 + relu -> A2[:,0:1024)
//                  AND l_out = relu(l @ W2 + b2) -> A2[:,1024:2048), both hi/lo ----------------
__global__ void reduce1_lout_kernel(const float* __restrict__ part,
                                    const float* __restrict__ b1,
                                    const float* __restrict__ l,
                                    const float* __restrict__ W2,
                                    const float* __restrict__ b2,
                                    __nv_bfloat16* __restrict__ A2h,
                                    __nv_bfloat16* __restrict__ A2l) {
    int idx = blockIdx.x * blockDim.x + threadIdx.x;   // 0 .. 256*2048-1
    int j = idx & (HOUT - 1);
    int b = idx >> 11;
    float s;
    if (j < HG) {
        s = b1[j];
        int pidx = b * HG + j;
        #pragma unroll
        for (int z = 0; z < SPLITK1; z++)
            s += part[(size_t)z * BATCH * HG + pidx];
    } else {
        int jl = j - HG;
        s = fmaf(l[b * 2 + 0], W2[jl], fmaf(l[b * 2 + 1], W2[HL + jl], b2[jl]));
    }
    s = fmaxf(s, 0.0f);
    split_store(s, A2h + idx, A2l + idx);
}

// ---------------- reduce GEMM2 partials + b3 + b4 + relu -> out ----------------
__global__ void reduce2_kernel(const float* __restrict__ part,
                               const float* __restrict__ b3,
                               const float* __restrict__ b4,
                               float* __restrict__ out) {
    int idx = blockIdx.x * blockDim.x + threadIdx.x;   // 0 .. 256*2048-1
    int j = idx & (HOUT - 1);
    float s = b3[j] + b4[j];
    #pragma unroll
    for (int z = 0; z < SPLITK2; z++)
        s += part[(size_t)z * BATCH * HOUT + idx];
    out[idx] = fmaxf(s, 0.0f);
}

// ---------------- launch ----------------
extern "C" void kernel_launch(void* const* d_in, const int* in_sizes, int n_in,
                              void* d_out, int out_size) {
    const float* x     = (const float*)d_in[0];
    const float* lprev = (const float*)d_in[1];
    const float* W1    = (const float*)d_in[2];
    const float* b1    = (const float*)d_in[3];
    const float* W2    = (const float*)d_in[4];
    const float* b2    = (const float*)d_in[5];
    const float* W3    = (const float*)d_in[6];
    const float* b3    = (const float*)d_in[7];
    const float* W4    = (const float*)d_in[8];
    const float* b4    = (const float*)d_in[9];
    float* out = (float*)d_out;

    __nv_bfloat16 *A1h, *A1l, *W1h, *W1l, *B2h, *B2l, *A2h, *A2l;
    float *part1, *part2;
    cudaGetSymbolAddress((void**)&A1h, g_A1hi);
    cudaGetSymbolAddress((void**)&A1l, g_A1lo);
    cudaGetSymbolAddress((void**)&W1h, g_W1hi);
    cudaGetSymbolAddress((void**)&W1l, g_W1lo);
    cudaGetSymbolAddress((void**)&B2h, g_B2hi);
    cudaGetSymbolAddress((void**)&B2l, g_B2lo);
    cudaGetSymbolAddress((void**)&A2h, g_A2hi);
    cudaGetSymbolAddress((void**)&A2l, g_A2lo);
    cudaGetSymbolAddress((void**)&part1, g_part1);
    cudaGetSymbolAddress((void**)&part2, g_part2);

    cudaFuncSetAttribute(hmma_gemm_kernel,
                         cudaFuncAttributeMaxDynamicSharedMemorySize, GEMM_SMEM);

    // 1. foveate -> A1 hi/lo (256, 9216)
    foveate_kernel<<<(BATCH * DIMG) / 256, 256>>>(x, lprev, A1h, A1l);

    // 2. weight conversions (independent)
    conv_w1_kernel<<<dim3(HG / 32, DIMG / 32), dim3(32, 8)>>>(W1, W1h, W1l);
    conv_b2_kernel<<<dim3(HOUT / 32, HOUT / 32), dim3(32, 8)>>>(W3, W4, B2h, B2l);

    // 3. GEMM1: (256x9216) @ (9216x1024), split-K=18 -> 288 CTAs (one 2-CTA/SM wave)
    hmma_gemm_kernel<<<dim3(HG / 128, BATCH / 128, SPLITK1), 128, GEMM_SMEM>>>(
        A1h, A1l, DIMG, W1h, W1l, DIMG, part1, HG, KCHUNK1);

    // 4. fused reduce + b1 + relu (left) and l_out (right) -> A2 hi/lo
    reduce1_lout_kernel<<<(BATCH * HOUT) / 256, 256>>>(part1, b1, lprev, W2, b2, A2h, A2l);

    // 5. GEMM2: (256x2048) @ (2048x2048), split-K=8 -> 256 CTAs
    hmma_gemm_kernel<<<dim3(HOUT / 128, BATCH / 128, SPLITK2), 128, GEMM_SMEM>>>(
        A2h, A2l, HOUT, B2h, B2l, HOUT, part2, HOUT, KCHUNK2);

    // 6. reduce + b3 + b4 + relu -> out
    reduce2_kernel<<<(BATCH * HOUT) / 256, 256>>>(part2, b3, b4, out);
}

// round 14
// speedup vs baseline: 2.4715x; 1.0252x over previous
#include <cuda_runtime.h>
#include <cuda_bf16.h>
#include <cstdint>

// ---------------- problem constants ----------------
#define BATCH 256
#define CHAN  3
#define IMG   224
#define DIMG  9216          // K of GEMM1
#define HG    1024
#define HL    1024
#define HOUT  2048
#define SPLITK1 18
#define KCHUNK1 (DIMG / SPLITK1)   // 512
#define SPLITK2 8
#define KCHUNK2 (HOUT / SPLITK2)   // 256

// ---------------- baseline-feature PTX helpers (sm_80+: valid on sm_103) ----------------
__device__ __forceinline__ uint32_t smem_to_u32(const void* p) {
    uint32_t a;
    asm("{ .reg .u64 t; cvta.to.shared.u64 t, %1; cvt.u32.u64 %0, t; }" : "=r"(a) : "l"(p));
    return a;
}
#define CP_ASYNC_16(dst, src) \
    asm volatile("cp.async.cg.shared.global [%0], [%1], 16;" :: "r"(dst), "l"(src))
#define CP_COMMIT asm volatile("cp.async.commit_group;" ::: "memory")
#define CP_WAIT(n) asm volatile("cp.async.wait_group %0;" :: "n"(n) : "memory")

__device__ __forceinline__ void ldsm_x4(uint32_t* r, uint32_t addr) {
    asm volatile("ldmatrix.sync.aligned.m8n8.x4.shared.b16 {%0,%1,%2,%3}, [%4];"
        : "=r"(r[0]), "=r"(r[1]), "=r"(r[2]), "=r"(r[3]) : "r"(addr));
}
__device__ __forceinline__ void mma_bf16(float* c, const uint32_t* a, const uint32_t* b) {
    asm volatile(
        "mma.sync.aligned.m16n8k16.row.col.f32.bf16.bf16.f32 "
        "{%0,%1,%2,%3}, {%4,%5,%6,%7}, {%8,%9}, {%0,%1,%2,%3};"
        : "+f"(c[0]), "+f"(c[1]), "+f"(c[2]), "+f"(c[3])
        : "r"(a[0]), "r"(a[1]), "r"(a[2]), "r"(a[3]), "r"(b[0]), "r"(b[1]));
}

// ---------------- scratch (device globals) ----------------
__device__ __align__(16) __nv_bfloat16 g_A1hi[BATCH * DIMG];
__device__ __align__(16) __nv_bfloat16 g_A1lo[BATCH * DIMG];
__device__ __align__(16) __nv_bfloat16 g_W1hi[HG * DIMG];     // (N=1024, K=9216)
__device__ __align__(16) __nv_bfloat16 g_W1lo[HG * DIMG];
__device__ __align__(16) __nv_bfloat16 g_B2hi[HOUT * HOUT];   // (N=2048, K=2048) = [W3;W4]^T
__device__ __align__(16) __nv_bfloat16 g_B2lo[HOUT * HOUT];
__device__ __align__(16) __nv_bfloat16 g_A2hi[BATCH * HOUT];
__device__ __align__(16) __nv_bfloat16 g_A2lo[BATCH * HOUT];
__device__ float g_part1[SPLITK1 * BATCH * HG];
__device__ float g_part2[SPLITK2 * BATCH * HOUT];

__device__ __forceinline__ void split_store(float v, __nv_bfloat16* hi_p, __nv_bfloat16* lo_p) {
    __nv_bfloat16 hi = __float2bfloat16(v);
    float r = v - __bfloat162float(hi);
    *hi_p = hi;
    *lo_p = __float2bfloat16(r);
}

// ---------------- foveate: glimpse extraction + pool, emit bf16 hi/lo ----------------
__global__ void foveate_kernel(const float* __restrict__ x,
                               const float* __restrict__ l,
                               __nv_bfloat16* __restrict__ ghi,
                               __nv_bfloat16* __restrict__ glo) {
    int idx = blockIdx.x * blockDim.x + threadIdx.x;   // 0 .. 256*9216-1
    int gx = idx & 31;
    int gy = (idx >> 5) & 31;
    int v  = idx >> 10;            // b*9 + k*3 + ch
    int ch = v % 3;
    int k  = (v / 3) % 3;
    int b  = v / 9;

    float l0 = l[b * 2 + 0];
    float l1 = l[b * 2 + 1];
    int sc = (int)(__fmul_rn(0.5f, __fmul_rn(__fadd_rn(l0, 1.0f), 224.0f)));
    int sr = (int)(__fmul_rn(0.5f, __fmul_rn(__fadd_rn(l1, 1.0f), 224.0f)));

    int p   = 1 << k;
    int pad = (16 << k) + 1;

    const float* xb = x + ((size_t)b * CHAN + ch) * IMG * IMG;
    int r0 = sr + gy * p - pad;
    int c0 = sc + gx * p - pad;

    float s = 0.0f;
    #pragma unroll 4
    for (int di = 0; di < p; di++) {
        int r = r0 + di;
        if (r < 0 || r >= IMG) continue;
        const float* row = xb + r * IMG;
        #pragma unroll 4
        for (int dj = 0; dj < p; dj++) {
            int c = c0 + dj;
            if (c >= 0 && c < IMG) s += row[c];
        }
    }
    s *= (1.0f / (float)(p * p));
    split_store(s, ghi + idx, glo + idx);
}

// ---------------- transpose + split W1 (9216,1024) -> (1024,9216) hi/lo ----------------
__global__ void conv_w1_kernel(const float* __restrict__ W,
                               __nv_bfloat16* __restrict__ Bh,
                               __nv_bfloat16* __restrict__ Bl) {
    __shared__ float s[32][33];
    int n0 = blockIdx.x * 32, k0 = blockIdx.y * 32;
    int tx = threadIdx.x, ty = threadIdx.y;   // 32 x 8
    #pragma unroll
    for (int i = 0; i < 32; i += 8)
        s[ty + i][tx] = W[(size_t)(k0 + ty + i) * HG + n0 + tx];
    __syncthreads();
    #pragma unroll
    for (int i = 0; i < 32; i += 8) {
        float v = s[tx][ty + i];   // = W[k0+tx][n0+ty+i]
        size_t o = (size_t)(n0 + ty + i) * DIMG + k0 + tx;
        split_store(v, Bh + o, Bl + o);
    }
}

// ---------------- transpose + split [W3;W4] (2048,2048) -> (2048,2048) hi/lo ----------------
__global__ void conv_b2_kernel(const float* __restrict__ W3,
                               const float* __restrict__ W4,
                               __nv_bfloat16* __restrict__ Bh,
                               __nv_bfloat16* __restrict__ Bl) {
    __shared__ float s[32][33];
    int n0 = blockIdx.x * 32, k0 = blockIdx.y * 32;
    int tx = threadIdx.x, ty = threadIdx.y;
    #pragma unroll
    for (int i = 0; i < 32; i += 8) {
        int k = k0 + ty + i;
        float v = (k < HG) ? W3[(size_t)k * HOUT + n0 + tx]
                           : W4[(size_t)(k - HG) * HOUT + n0 + tx];
        s[ty + i][tx] = v;
    }
    __syncthreads();
    #pragma unroll
    for (int i = 0; i < 32; i += 8) {
        float v = s[tx][ty + i];
        size_t o = (size_t)(n0 + ty + i) * HOUT + k0 + tx;
        split_store(v, Bh + o, Bl + o);
    }
}

// ---------------- HMMA split-precision GEMM ----------------
// CTA: 128x128 tile, BK=32, 8 warps (2 in M x 4 in N), warp tile 64x32,
// double-buffered cp.async, 2 CTAs/SM (16 warps/SM = 4/SMSP).
// A: (M, lda) K-major bf16 hi/lo. B: (N, ldb) K-major.
// C_partial[z] = Ahi*Bhi + Ahi*Blo + Alo*Bhi over K range [z*kPerSplit, ...)
#define AS_STRIDE_B 80                       // bytes per smem row (64B data + 16B pad)
#define TILE_B (128 * AS_STRIDE_B)           // 10240
#define SM_AHI 0
#define SM_ALO TILE_B
#define SM_BHI (2 * TILE_B)
#define SM_BLO (3 * TILE_B)
#define STAGE_B (4 * TILE_B)                 // 40960
#define GEMM_SMEM (2 * STAGE_B)              // 81920

// 128 rows x 64B, 256 threads: 512 chunks of 16B -> 2 per thread
__device__ __forceinline__ void cp_tile128(uint32_t dst_base, const __nv_bfloat16* src,
                                           int row0, int ld, int kt, int tid) {
    #pragma unroll
    for (int i = 0; i < 2; i++) {
        int c = i * 256 + tid;
        int r = c >> 2, seg = c & 3;
        uint32_t dst = dst_base + r * AS_STRIDE_B + seg * 16;
        const void* s = src + (size_t)(row0 + r) * ld + kt + seg * 8;
        CP_ASYNC_16(dst, s);
    }
}

__global__ void __launch_bounds__(256, 2)
hmma_gemm_kernel(const __nv_bfloat16* __restrict__ Ahi, const __nv_bfloat16* __restrict__ Alo, int lda,
                 const __nv_bfloat16* __restrict__ Bhi, const __nv_bfloat16* __restrict__ Blo, int ldb,
                 float* __restrict__ Cpart, int N, int kPerSplit) {
    extern __shared__ char smem[];
    uint32_t sb = smem_to_u32(smem);
    int tid = threadIdx.x, lane = tid & 31;
    int wid = tid >> 5;
    int wm = wid & 1;            // 2 warps in M: rows wm*64 .. wm*64+63
    int wn = wid >> 1;           // 4 warps in N: cols wn*32 .. wn*32+31

    int m0 = blockIdx.y * 128;
    int n0 = blockIdx.x * 128;
    int z  = blockIdx.z;
    int k0 = z * kPerSplit;
    int nt = kPerSplit >> 5;     // BK=32 steps

    float acc[4][4][4];
    #pragma unroll
    for (int a = 0; a < 4; a++)
        #pragma unroll
        for (int b = 0; b < 4; b++)
            #pragma unroll
            for (int c = 0; c < 4; c++) acc[a][b][c] = 0.0f;

    // prefetch stage 0
    {
        uint32_t base = sb;
        cp_tile128(base + SM_AHI, Ahi, m0, lda, k0, tid);
        cp_tile128(base + SM_ALO, Alo, m0, lda, k0, tid);
        cp_tile128(base + SM_BHI, Bhi, n0, ldb, k0, tid);
        cp_tile128(base + SM_BLO, Blo, n0, ldb, k0, tid);
        CP_COMMIT;
    }

    for (int t = 0; t < nt; t++) {
        if (t + 1 < nt) {
            uint32_t base = sb + ((t + 1) & 1) * STAGE_B;
            int kt = k0 + (t + 1) * 32;
            cp_tile128(base + SM_AHI, Ahi, m0, lda, kt, tid);
            cp_tile128(base + SM_ALO, Alo, m0, lda, kt, tid);
            cp_tile128(base + SM_BHI, Bhi, n0, ldb, kt, tid);
            cp_tile128(base + SM_BLO, Blo, n0, ldb, kt, tid);
            CP_COMMIT;
            CP_WAIT(1);
        } else {
            CP_WAIT(0);
        }
        __syncthreads();

        uint32_t base = sb + (t & 1) * STAGE_B;
        #pragma unroll
        for (int kk = 0; kk < 32; kk += 16) {
            uint32_t ah[4][4], al[4][4];
            #pragma unroll
            for (int mt = 0; mt < 4; mt++) {
                int row = wm * 64 + mt * 16 + (lane & 15);
                uint32_t off = row * AS_STRIDE_B + (kk + (lane >> 4) * 8) * 2;
                ldsm_x4(ah[mt], base + SM_AHI + off);
                ldsm_x4(al[mt], base + SM_ALO + off);
            }
            #pragma unroll
            for (int ng = 0; ng < 2; ng++) {
                uint32_t bh[4], bl[4];
                int nrow = wn * 32 + ng * 16 + ((lane >> 4) << 3) + (lane & 7);
                uint32_t off = nrow * AS_STRIDE_B + (kk + ((lane >> 3) & 1) * 8) * 2;
                ldsm_x4(bh, base + SM_BHI + off);
                ldsm_x4(bl, base + SM_BLO + off);
                #pragma unroll
                for (int mt = 0; mt < 4; mt++) {
                    #pragma unroll
                    for (int half = 0; half < 2; half++) {
                        float* c = acc[mt][ng * 2 + half];
                        mma_bf16(c, ah[mt], bh + half * 2);
                        mma_bf16(c, ah[mt], bl + half * 2);
                        mma_bf16(c, al[mt], bh + half * 2);
                    }
                }
            }
        }
        __syncthreads();
    }

    // epilogue: write fp32 partials
    float* C = Cpart + ((size_t)z * BATCH + m0) * N + n0;
    #pragma unroll
    for (int mt = 0; mt < 4; mt++) {
        int r0 = wm * 64 + mt * 16 + (lane >> 2);
        #pragma unroll
        for (int j = 0; j < 4; j++) {
            int col = wn * 32 + j * 8 + (lane & 3) * 2;
            float* c = acc[mt][j];
            *(float2*)(C + (size_t)r0 * N + col)       = make_float2(c[0], c[1]);
            *(float2*)(C + (size_t)(r0 + 8) * N + col) = make_float2(c[2], c[3]);
        }
    }
}

// ---------------- fused: reduce GEMM1 partials + b1 + relu -> A2[:,0:1024)
//                  AND l_out = relu(l @ W2 + b2) -> A2[:,1024:2048), both hi/lo ----------------
__global__ void reduce1_lout_kernel(const float* __restrict__ part,
                                    const float* __restrict__ b1,
                                    const float* __restrict__ l,
                                    const float* __restrict__ W2,
                                    const float* __restrict__ b2,
                                    __nv_bfloat16* __restrict__ A2h,
                                    __nv_bfloat16* __restrict__ A2l) {
    int idx = blockIdx.x * blockDim.x + threadIdx.x;   // 0 .. 256*2048-1
    int j = idx & (HOUT - 1);
    int b = idx >> 11;
    float s;
    if (j < HG) {
        s = b1[j];
        int pidx = b * HG + j;
        #pragma unroll
        for (int z = 0; z < SPLITK1; z++)
            s += part[(size_t)z * BATCH * HG + pidx];
    } else {
        int jl = j - HG;
        s = fmaf(l[b * 2 + 0], W2[jl], fmaf(l[b * 2 + 1], W2[HL + jl], b2[jl]));
    }
    s = fmaxf(s, 0.0f);
    split_store(s, A2h + idx, A2l + idx);
}

// ---------------- reduce GEMM2 partials + b3 + b4 + relu -> out ----------------
__global__ void reduce2_kernel(const float* __restrict__ part,
                               const float* __restrict__ b3,
                               const float* __restrict__ b4,
                               float* __restrict__ out) {
    int idx = blockIdx.x * blockDim.x + threadIdx.x;   // 0 .. 256*2048-1
    int j = idx & (HOUT - 1);
    float s = b3[j] + b4[j];
    #pragma unroll
    for (int z = 0; z < SPLITK2; z++)
        s += part[(size_t)z * BATCH * HOUT + idx];
    out[idx] = fmaxf(s, 0.0f);
}

// ---------------- launch ----------------
extern "C" void kernel_launch(void* const* d_in, const int* in_sizes, int n_in,
                              void* d_out, int out_size) {
    const float* x     = (const float*)d_in[0];
    const float* lprev = (const float*)d_in[1];
    const float* W1    = (const float*)d_in[2];
    const float* b1    = (const float*)d_in[3];
    const float* W2    = (const float*)d_in[4];
    const float* b2    = (const float*)d_in[5];
    const float* W3    = (const float*)d_in[6];
    const float* b3    = (const float*)d_in[7];
    const float* W4    = (const float*)d_in[8];
    const float* b4    = (const float*)d_in[9];
    float* out = (float*)d_out;

    __nv_bfloat16 *A1h, *A1l, *W1h, *W1l, *B2h, *B2l, *A2h, *A2l;
    float *part1, *part2;
    cudaGetSymbolAddress((void**)&A1h, g_A1hi);
    cudaGetSymbolAddress((void**)&A1l, g_A1lo);
    cudaGetSymbolAddress((void**)&W1h, g_W1hi);
    cudaGetSymbolAddress((void**)&W1l, g_W1lo);
    cudaGetSymbolAddress((void**)&B2h, g_B2hi);
    cudaGetSymbolAddress((void**)&B2l, g_B2lo);
    cudaGetSymbolAddress((void**)&A2h, g_A2hi);
    cudaGetSymbolAddress((void**)&A2l, g_A2lo);
    cudaGetSymbolAddress((void**)&part1, g_part1);
    cudaGetSymbolAddress((void**)&part2, g_part2);

    cudaFuncSetAttribute(hmma_gemm_kernel,
                         cudaFuncAttributeMaxDynamicSharedMemorySize, GEMM_SMEM);

    // 1. foveate -> A1 hi/lo (256, 9216)
    foveate_kernel<<<(BATCH * DIMG) / 256, 256>>>(x, lprev, A1h, A1l);

    // 2. weight conversions (independent)
    conv_w1_kernel<<<dim3(HG / 32, DIMG / 32), dim3(32, 8)>>>(W1, W1h, W1l);
    conv_b2_kernel<<<dim3(HOUT / 32, HOUT / 32), dim3(32, 8)>>>(W3, W4, B2h, B2l);

    // 3. GEMM1: (256x9216) @ (9216x1024), split-K=18 -> 288 CTAs (2 CTAs/SM wave)
    hmma_gemm_kernel<<<dim3(HG / 128, BATCH / 128, SPLITK1), 256, GEMM_SMEM>>>(
        A1h, A1l, DIMG, W1h, W1l, DIMG, part1, HG, KCHUNK1);

    // 4. fused reduce + b1 + relu (left) and l_out (right) -> A2 hi/lo
    reduce1_lout_kernel<<<(BATCH * HOUT) / 256, 256>>>(part1, b1, lprev, W2, b2, A2h, A2l);

    // 5. GEMM2: (256x2048) @ (2048x2048), split-K=8 -> 256 CTAs
    hmma_gemm_kernel<<<dim3(HOUT / 128, BATCH / 128, SPLITK2), 256, GEMM_SMEM>>>(
        A2h, A2l, HOUT, B2h, B2l, HOUT, part2, HOUT, KCHUNK2);

    // 6. reduce + b3 + b4 + relu -> out
    reduce2_kernel<<<(BATCH * HOUT) / 256, 256>>>(part2, b3, b4, out);
}

// round 15
// speedup vs baseline: 3.4979x; 1.4153x over previous
#include <cuda_runtime.h>
#include <cuda_fp16.h>
#include <cstdint>

// ---------------- problem constants ----------------
#define BATCH 256
#define CHAN  3
#define IMG   224
#define DIMG  9216          // K of GEMM1
#define HG    1024
#define HL    1024
#define HOUT  2048
#define SPLITK1 18
#define KCHUNK1 (DIMG / SPLITK1)   // 512
#define SPLITK2 8
#define KCHUNK2 (HOUT / SPLITK2)   // 256

// ---------------- baseline-feature PTX helpers (sm_80+: valid on sm_103) ----------------
__device__ __forceinline__ uint32_t smem_to_u32(const void* p) {
    uint32_t a;
    asm("{ .reg .u64 t; cvta.to.shared.u64 t, %1; cvt.u32.u64 %0, t; }" : "=r"(a) : "l"(p));
    return a;
}
#define CP_ASYNC_16(dst, src) \
    asm volatile("cp.async.cg.shared.global [%0], [%1], 16;" :: "r"(dst), "l"(src))
#define CP_COMMIT asm volatile("cp.async.commit_group;" ::: "memory")
#define CP_WAIT(n) asm volatile("cp.async.wait_group %0;" :: "n"(n) : "memory")

__device__ __forceinline__ void ldsm_x4(uint32_t* r, uint32_t addr) {
    asm volatile("ldmatrix.sync.aligned.m8n8.x4.shared.b16 {%0,%1,%2,%3}, [%4];"
        : "=r"(r[0]), "=r"(r[1]), "=r"(r[2]), "=r"(r[3]) : "r"(addr));
}
__device__ __forceinline__ void mma_fp16(float* c, const uint32_t* a, const uint32_t* b) {
    asm volatile(
        "mma.sync.aligned.m16n8k16.row.col.f32.f16.f16.f32 "
        "{%0,%1,%2,%3}, {%4,%5,%6,%7}, {%8,%9}, {%0,%1,%2,%3};"
        : "+f"(c[0]), "+f"(c[1]), "+f"(c[2]), "+f"(c[3])
        : "r"(a[0]), "r"(a[1]), "r"(a[2]), "r"(a[3]), "r"(b[0]), "r"(b[1]));
}

// ---------------- scratch (device globals) ----------------
__device__ __align__(16) __half g_A1[BATCH * DIMG];
__device__ __align__(16) __half g_W1[HG * DIMG];     // (N=1024, K=9216)
__device__ __align__(16) __half g_B2[HOUT * HOUT];   // (N=2048, K=2048) = [W3;W4]^T
__device__ __align__(16) __half g_A2[BATCH * HOUT];
__device__ float g_part1[SPLITK1 * BATCH * HG];
__device__ float g_part2[SPLITK2 * BATCH * HOUT];

// ---------------- foveate: glimpse extraction + pool, emit fp16 ----------------
__global__ void foveate_kernel(const float* __restrict__ x,
                               const float* __restrict__ l,
                               __half* __restrict__ g) {
    int idx = blockIdx.x * blockDim.x + threadIdx.x;   // 0 .. 256*9216-1
    int gx = idx & 31;
    int gy = (idx >> 5) & 31;
    int v  = idx >> 10;            // b*9 + k*3 + ch
    int ch = v % 3;
    int k  = (v / 3) % 3;
    int b  = v / 9;

    float l0 = l[b * 2 + 0];
    float l1 = l[b * 2 + 1];
    int sc = (int)(__fmul_rn(0.5f, __fmul_rn(__fadd_rn(l0, 1.0f), 224.0f)));
    int sr = (int)(__fmul_rn(0.5f, __fmul_rn(__fadd_rn(l1, 1.0f), 224.0f)));

    int p   = 1 << k;
    int pad = (16 << k) + 1;

    const float* xb = x + ((size_t)b * CHAN + ch) * IMG * IMG;
    int r0 = sr + gy * p - pad;
    int c0 = sc + gx * p - pad;

    float s = 0.0f;
    #pragma unroll 4
    for (int di = 0; di < p; di++) {
        int r = r0 + di;
        if (r < 0 || r >= IMG) continue;
        const float* row = xb + r * IMG;
        #pragma unroll 4
        for (int dj = 0; dj < p; dj++) {
            int c = c0 + dj;
            if (c >= 0 && c < IMG) s += row[c];
        }
    }
    s *= (1.0f / (float)(p * p));
    g[idx] = __float2half_rn(s);
}

// ---------------- transpose W1 (9216,1024) -> (1024,9216) fp16 ----------------
__global__ void conv_w1_kernel(const float* __restrict__ W,
                               __half* __restrict__ B) {
    __shared__ float s[32][33];
    int n0 = blockIdx.x * 32, k0 = blockIdx.y * 32;
    int tx = threadIdx.x, ty = threadIdx.y;   // 32 x 8
    #pragma unroll
    for (int i = 0; i < 32; i += 8)
        s[ty + i][tx] = W[(size_t)(k0 + ty + i) * HG + n0 + tx];
    __syncthreads();
    #pragma unroll
    for (int i = 0; i < 32; i += 8) {
        float v = s[tx][ty + i];   // = W[k0+tx][n0+ty+i]
        B[(size_t)(n0 + ty + i) * DIMG + k0 + tx] = __float2half_rn(v);
    }
}

// ---------------- transpose [W3;W4] (2048,2048) -> (2048,2048) fp16 ----------------
__global__ void conv_b2_kernel(const float* __restrict__ W3,
                               const float* __restrict__ W4,
                               __half* __restrict__ B) {
    __shared__ float s[32][33];
    int n0 = blockIdx.x * 32, k0 = blockIdx.y * 32;
    int tx = threadIdx.x, ty = threadIdx.y;
    #pragma unroll
    for (int i = 0; i < 32; i += 8) {
        int k = k0 + ty + i;
        float v = (k < HG) ? W3[(size_t)k * HOUT + n0 + tx]
                           : W4[(size_t)(k - HG) * HOUT + n0 + tx];
        s[ty + i][tx] = v;
    }
    __syncthreads();
    #pragma unroll
    for (int i = 0; i < 32; i += 8) {
        float v = s[tx][ty + i];
        B[(size_t)(n0 + ty + i) * HOUT + k0 + tx] = __float2half_rn(v);
    }
}

// ---------------- HMMA fp16 GEMM ----------------
// CTA: 128x128 tile, BK=32, 8 warps (2 in M x 4 in N), warp tile 64x32,
// double-buffered cp.async, 2 CTAs/SM. A: (M, lda) K-major fp16. B: (N, ldb) K-major.
// C_partial[z] = A @ B^T over K range [z*kPerSplit, (z+1)*kPerSplit)
#define AS_STRIDE_B 80                       // bytes per smem row (64B data + 16B pad)
#define TILE_B (128 * AS_STRIDE_B)           // 10240
#define SM_A 0
#define SM_B TILE_B
#define STAGE_B (2 * TILE_B)                 // 20480
#define GEMM_SMEM (2 * STAGE_B)              // 40960

// 128 rows x 64B, 256 threads: 512 chunks of 16B -> 2 per thread
__device__ __forceinline__ void cp_tile128(uint32_t dst_base, const __half* src,
                                           int row0, int ld, int kt, int tid) {
    #pragma unroll
    for (int i = 0; i < 2; i++) {
        int c = i * 256 + tid;
        int r = c >> 2, seg = c & 3;
        uint32_t dst = dst_base + r * AS_STRIDE_B + seg * 16;
        const void* s = src + (size_t)(row0 + r) * ld + kt + seg * 8;
        CP_ASYNC_16(dst, s);
    }
}

__global__ void __launch_bounds__(256, 2)
hmma_gemm_kernel(const __half* __restrict__ A, int lda,
                 const __half* __restrict__ B, int ldb,
                 float* __restrict__ Cpart, int N, int kPerSplit) {
    extern __shared__ char smem[];
    uint32_t sb = smem_to_u32(smem);
    int tid = threadIdx.x, lane = tid & 31;
    int wid = tid >> 5;
    int wm = wid & 1;            // 2 warps in M: rows wm*64 .. wm*64+63
    int wn = wid >> 1;           // 4 warps in N: cols wn*32 .. wn*32+31

    int m0 = blockIdx.y * 128;
    int n0 = blockIdx.x * 128;
    int z  = blockIdx.z;
    int k0 = z * kPerSplit;
    int nt = kPerSplit >> 5;     // BK=32 steps

    float acc[4][4][4];
    #pragma unroll
    for (int a = 0; a < 4; a++)
        #pragma unroll
        for (int b = 0; b < 4; b++)
            #pragma unroll
            for (int c = 0; c < 4; c++) acc[a][b][c] = 0.0f;

    // prefetch stage 0
    {
        uint32_t base = sb;
        cp_tile128(base + SM_A, A, m0, lda, k0, tid);
        cp_tile128(base + SM_B, B, n0, ldb, k0, tid);
        CP_COMMIT;
    }

    for (int t = 0; t < nt; t++) {
        if (t + 1 < nt) {
            uint32_t base = sb + ((t + 1) & 1) * STAGE_B;
            int kt = k0 + (t + 1) * 32;
            cp_tile128(base + SM_A, A, m0, lda, kt, tid);
            cp_tile128(base + SM_B, B, n0, ldb, kt, tid);
            CP_COMMIT;
            CP_WAIT(1);
        } else {
            CP_WAIT(0);
        }
        __syncthreads();

        uint32_t base = sb + (t & 1) * STAGE_B;
        #pragma unroll
        for (int kk = 0; kk < 32; kk += 16) {
            uint32_t ah[4][4];
            #pragma unroll
            for (int mt = 0; mt < 4; mt++) {
                int row = wm * 64 + mt * 16 + (lane & 15);
                uint32_t off = row * AS_STRIDE_B + (kk + (lane >> 4) * 8) * 2;
                ldsm_x4(ah[mt], base + SM_A + off);
            }
            #pragma unroll
            for (int ng = 0; ng < 2; ng++) {
                uint32_t bh[4];
                int nrow = wn * 32 + ng * 16 + ((lane >> 4) << 3) + (lane & 7);
                uint32_t off = nrow * AS_STRIDE_B + (kk + ((lane >> 3) & 1) * 8) * 2;
                ldsm_x4(bh, base + SM_B + off);
                #pragma unroll
                for (int mt = 0; mt < 4; mt++) {
                    #pragma unroll
                    for (int half = 0; half < 2; half++) {
                        mma_fp16(acc[mt][ng * 2 + half], ah[mt], bh + half * 2);
                    }
                }
            }
        }
        __syncthreads();
    }

    // epilogue: write fp32 partials
    float* C = Cpart + ((size_t)z * BATCH + m0) * N + n0;
    #pragma unroll
    for (int mt = 0; mt < 4; mt++) {
        int r0 = wm * 64 + mt * 16 + (lane >> 2);
        #pragma unroll
        for (int j = 0; j < 4; j++) {
            int col = wn * 32 + j * 8 + (lane & 3) * 2;
            float* c = acc[mt][j];
            *(float2*)(C + (size_t)r0 * N + col)       = make_float2(c[0], c[1]);
            *(float2*)(C + (size_t)(r0 + 8) * N + col) = make_float2(c[2], c[3]);
        }
    }
}

// ---------------- fused: reduce GEMM1 partials + b1 + relu -> A2[:,0:1024)
//                  AND l_out = relu(l @ W2 + b2) -> A2[:,1024:2048), fp16 ----------------
__global__ void reduce1_lout_kernel(const float* __restrict__ part,
                                    const float* __restrict__ b1,
                                    const float* __restrict__ l,
                                    const float* __restrict__ W2,
                                    const float* __restrict__ b2,
                                    __half* __restrict__ A2) {
    int idx = blockIdx.x * blockDim.x + threadIdx.x;   // 0 .. 256*2048-1
    int j = idx & (HOUT - 1);
    int b = idx >> 11;
    float s;
    if (j < HG) {
        s = b1[j];
        int pidx = b * HG + j;
        #pragma unroll
        for (int z = 0; z < SPLITK1; z++)
            s += part[(size_t)z * BATCH * HG + pidx];
    } else {
        int jl = j - HG;
        s = fmaf(l[b * 2 + 0], W2[jl], fmaf(l[b * 2 + 1], W2[HL + jl], b2[jl]));
    }
    s = fmaxf(s, 0.0f);
    A2[idx] = __float2half_rn(s);
}

// ---------------- reduce GEMM2 partials + b3 + b4 + relu -> out ----------------
__global__ void reduce2_kernel(const float* __restrict__ part,
                               const float* __restrict__ b3,
                               const float* __restrict__ b4,
                               float* __restrict__ out) {
    int idx = blockIdx.x * blockDim.x + threadIdx.x;   // 0 .. 256*2048-1
    int j = idx & (HOUT - 1);
    float s = b3[j] + b4[j];
    #pragma unroll
    for (int z = 0; z < SPLITK2; z++)
        s += part[(size_t)z * BATCH * HOUT + idx];
    out[idx] = fmaxf(s, 0.0f);
}

// ---------------- launch ----------------
extern "C" void kernel_launch(void* const* d_in, const int* in_sizes, int n_in,
                              void* d_out, int out_size) {
    const float* x     = (const float*)d_in[0];
    const float* lprev = (const float*)d_in[1];
    const float* W1    = (const float*)d_in[2];
    const float* b1    = (const float*)d_in[3];
    const float* W2    = (const float*)d_in[4];
    const float* b2    = (const float*)d_in[5];
    const float* W3    = (const float*)d_in[6];
    const float* b3    = (const float*)d_in[7];
    const float* W4    = (const float*)d_in[8];
    const float* b4    = (const float*)d_in[9];
    float* out = (float*)d_out;

    __half *A1, *W1h, *B2, *A2;
    float *part1, *part2;
    cudaGetSymbolAddress((void**)&A1,  g_A1);
    cudaGetSymbolAddress((void**)&W1h, g_W1);
    cudaGetSymbolAddress((void**)&B2,  g_B2);
    cudaGetSymbolAddress((void**)&A2,  g_A2);
    cudaGetSymbolAddress((void**)&part1, g_part1);
    cudaGetSymbolAddress((void**)&part2, g_part2);

    cudaFuncSetAttribute(hmma_gemm_kernel,
                         cudaFuncAttributeMaxDynamicSharedMemorySize, GEMM_SMEM);

    // 1. foveate -> A1 fp16 (256, 9216)
    foveate_kernel<<<(BATCH * DIMG) / 256, 256>>>(x, lprev, A1);

    // 2. weight conversions (independent)
    conv_w1_kernel<<<dim3(HG / 32, DIMG / 32), dim3(32, 8)>>>(W1, W1h);
    conv_b2_kernel<<<dim3(HOUT / 32, HOUT / 32), dim3(32, 8)>>>(W3, W4, B2);

    // 3. GEMM1: (256x9216) @ (9216x1024), split-K=18 -> 288 CTAs
    hmma_gemm_kernel<<<dim3(HG / 128, BATCH / 128, SPLITK1), 256, GEMM_SMEM>>>(
        A1, DIMG, W1h, DIMG, part1, HG, KCHUNK1);

    // 4. fused reduce + b1 + relu (left) and l_out (right) -> A2 fp16
    reduce1_lout_kernel<<<(BATCH * HOUT) / 256, 256>>>(part1, b1, lprev, W2, b2, A2);

    // 5. GEMM2: (256x2048) @ (2048x2048), split-K=8 -> 256 CTAs
    hmma_gemm_kernel<<<dim3(HOUT / 128, BATCH / 128, SPLITK2), 256, GEMM_SMEM>>>(
        A2, HOUT, B2, HOUT, part2, HOUT, KCHUNK2);

    // 6. reduce + b3 + b4 + relu -> out
    reduce2_kernel<<<(BATCH * HOUT) / 256, 256>>>(part2, b3, b4, out);
}

// round 17
// speedup vs baseline: 3.7601x; 1.0749x over previous
#include <cuda_runtime.h>
#include <cuda_fp16.h>
#include <cstdint>

// ---------------- problem constants ----------------
#define BATCH 256
#define CHAN  3
#define IMG   224
#define DIMG  9216          // K of GEMM1
#define HG    1024
#define HL    1024
#define HOUT  2048
#define SPLITK1 18
#define KCHUNK1 (DIMG / SPLITK1)   // 512
#define SPLITK2 8
#define KCHUNK2 (HOUT / SPLITK2)   // 256

// ---------------- baseline-feature PTX helpers (sm_80+: valid on sm_103) ----------------
__device__ __forceinline__ uint32_t smem_to_u32(const void* p) {
    uint32_t a;
    asm("{ .reg .u64 t; cvta.to.shared.u64 t, %1; cvt.u32.u64 %0, t; }" : "=r"(a) : "l"(p));
    return a;
}
#define CP_ASYNC_16(dst, src) \
    asm volatile("cp.async.cg.shared.global [%0], [%1], 16;" :: "r"(dst), "l"(src))
#define CP_COMMIT asm volatile("cp.async.commit_group;" ::: "memory")
#define CP_WAIT(n) asm volatile("cp.async.wait_group %0;" :: "n"(n) : "memory")

__device__ __forceinline__ void ldsm_x4(uint32_t* r, uint32_t addr) {
    asm volatile("ldmatrix.sync.aligned.m8n8.x4.shared.b16 {%0,%1,%2,%3}, [%4];"
        : "=r"(r[0]), "=r"(r[1]), "=r"(r[2]), "=r"(r[3]) : "r"(addr));
}
__device__ __forceinline__ void mma_fp16(float* c, const uint32_t* a, const uint32_t* b) {
    asm volatile(
        "mma.sync.aligned.m16n8k16.row.col.f32.f16.f16.f32 "
        "{%0,%1,%2,%3}, {%4,%5,%6,%7}, {%8,%9}, {%0,%1,%2,%3};"
        : "+f"(c[0]), "+f"(c[1]), "+f"(c[2]), "+f"(c[3])
        : "r"(a[0]), "r"(a[1]), "r"(a[2]), "r"(a[3]), "r"(b[0]), "r"(b[1]));
}

// ---------------- scratch (device globals) ----------------
__device__ __align__(16) __half g_A1[BATCH * DIMG];
__device__ __align__(16) __half g_W1[HG * DIMG];     // (N=1024, K=9216)
__device__ __align__(16) __half g_B2[HOUT * HOUT];   // (N=2048, K=2048) = [W3;W4]^T
__device__ __align__(16) __half g_A2[BATCH * HOUT];
__device__ float g_part1[SPLITK1 * BATCH * HG];
__device__ float g_part2[SPLITK2 * BATCH * HOUT];

// ---------------- fused prep: foveate + W1 transpose + [W3;W4] transpose ----------------
// block ranges: [0, 9216)               foveate   (256 thr linear)
//               [9216, 9216+9216)       conv_w1   (32x8 reindexed)
//               [18432, 18432+4096)     conv_b2
#define NB_FOV  (BATCH * DIMG / 256)          // 9216
#define NB_W1   ((HG / 32) * (DIMG / 32))     // 32*288 = 9216
#define NB_B2   ((HOUT / 32) * (HOUT / 32))   // 4096

__global__ void prep_kernel(const float* __restrict__ x,
                            const float* __restrict__ l,
                            const float* __restrict__ W1,
                            const float* __restrict__ W3,
                            const float* __restrict__ W4,
                            __half* __restrict__ A1,
                            __half* __restrict__ W1h,
                            __half* __restrict__ B2) {
    int blk = blockIdx.x;
    int tid = threadIdx.x;
    if (blk < NB_FOV) {
        // ---- foveate ----
        int idx = blk * 256 + tid;
        int gx = idx & 31;
        int gy = (idx >> 5) & 31;
        int v  = idx >> 10;            // b*9 + k*3 + ch
        int ch = v % 3;
        int k  = (v / 3) % 3;
        int b  = v / 9;

        float l0 = l[b * 2 + 0];
        float l1 = l[b * 2 + 1];
        int sc = (int)(__fmul_rn(0.5f, __fmul_rn(__fadd_rn(l0, 1.0f), 224.0f)));
        int sr = (int)(__fmul_rn(0.5f, __fmul_rn(__fadd_rn(l1, 1.0f), 224.0f)));

        int p   = 1 << k;
        int pad = (16 << k) + 1;

        const float* xb = x + ((size_t)b * CHAN + ch) * IMG * IMG;
        int r0 = sr + gy * p - pad;
        int c0 = sc + gx * p - pad;

        float s = 0.0f;
        #pragma unroll 4
        for (int di = 0; di < p; di++) {
            int r = r0 + di;
            if (r < 0 || r >= IMG) continue;
            const float* row = xb + r * IMG;
            #pragma unroll 4
            for (int dj = 0; dj < p; dj++) {
                int c = c0 + dj;
                if (c >= 0 && c < IMG) s += row[c];
            }
        }
        s *= (1.0f / (float)(p * p));
        A1[idx] = __float2half_rn(s);
    } else if (blk < NB_FOV + NB_W1) {
        // ---- transpose W1 (9216,1024) -> (1024,9216) fp16 ----
        __shared__ float sm[32][33];
        int bb = blk - NB_FOV;
        int n0 = (bb % (HG / 32)) * 32;
        int k0 = (bb / (HG / 32)) * 32;
        int tx = tid & 31, ty = tid >> 5;   // 32 x 8
        #pragma unroll
        for (int i = 0; i < 32; i += 8)
            sm[ty + i][tx] = W1[(size_t)(k0 + ty + i) * HG + n0 + tx];
        __syncthreads();
        #pragma unroll
        for (int i = 0; i < 32; i += 8) {
            float v = sm[tx][ty + i];   // = W1[k0+tx][n0+ty+i]
            W1h[(size_t)(n0 + ty + i) * DIMG + k0 + tx] = __float2half_rn(v);
        }
    } else {
        // ---- transpose [W3;W4] (2048,2048) -> (2048,2048) fp16 ----
        __shared__ float sm[32][33];
        int bb = blk - NB_FOV - NB_W1;
        int n0 = (bb % (HOUT / 32)) * 32;
        int k0 = (bb / (HOUT / 32)) * 32;
        int tx = tid & 31, ty = tid >> 5;
        #pragma unroll
        for (int i = 0; i < 32; i += 8) {
            int k = k0 + ty + i;
            float v = (k < HG) ? W3[(size_t)k * HOUT + n0 + tx]
                               : W4[(size_t)(k - HG) * HOUT + n0 + tx];
            sm[ty + i][tx] = v;
        }
        __syncthreads();
        #pragma unroll
        for (int i = 0; i < 32; i += 8) {
            float v = sm[tx][ty + i];
            B2[(size_t)(n0 + ty + i) * HOUT + k0 + tx] = __float2half_rn(v);
        }
    }
}

// ---------------- HMMA fp16 GEMM ----------------
// CTA: 128x128 tile, BK=32, 4 warps (2 in M x 2 in N), warp tile 64x64,
// double-buffered cp.async, 2 CTAs/SM. A: (M, lda) K-major fp16. B: (N, ldb) K-major.
// C_partial[z] = A @ B^T over K range [z*kPerSplit, (z+1)*kPerSplit)
#define AS_STRIDE_B 80                       // bytes per smem row (64B data + 16B pad)
#define TILE_B (128 * AS_STRIDE_B)           // 10240
#define SM_A 0
#define SM_B TILE_B
#define STAGE_B (2 * TILE_B)                 // 20480
#define GEMM_SMEM (2 * STAGE_B)              // 40960

// 128 rows x 64B, 128 threads: 512 chunks of 16B -> 4 per thread
__device__ __forceinline__ void cp_tile128(uint32_t dst_base, const __half* src,
                                           int row0, int ld, int kt, int tid) {
    #pragma unroll
    for (int i = 0; i < 4; i++) {
        int c = i * 128 + tid;
        int r = c >> 2, seg = c & 3;
        uint32_t dst = dst_base + r * AS_STRIDE_B + seg * 16;
        const void* s = src + (size_t)(row0 + r) * ld + kt + seg * 8;
        CP_ASYNC_16(dst, s);
    }
}

__global__ void __launch_bounds__(128, 2)
hmma_gemm_kernel(const __half* __restrict__ A, int lda,
                 const __half* __restrict__ B, int ldb,
                 float* __restrict__ Cpart, int N, int kPerSplit) {
    extern __shared__ char smem[];
    uint32_t sb = smem_to_u32(smem);
    int tid = threadIdx.x, lane = tid & 31;
    int wid = tid >> 5;
    int wm = wid & 1;            // 2 warps in M: rows wm*64 .. wm*64+63
    int wn = wid >> 1;           // 2 warps in N: cols wn*64 .. wn*64+63

    int m0 = blockIdx.y * 128;
    int n0 = blockIdx.x * 128;
    int z  = blockIdx.z;
    int k0 = z * kPerSplit;
    int nt = kPerSplit >> 5;     // BK=32 steps

    float acc[4][8][4];
    #pragma unroll
    for (int a = 0; a < 4; a++)
        #pragma unroll
        for (int b = 0; b < 8; b++)
            #pragma unroll
            for (int c = 0; c < 4; c++) acc[a][b][c] = 0.0f;

    // prefetch stage 0
    {
        uint32_t base = sb;
        cp_tile128(base + SM_A, A, m0, lda, k0, tid);
        cp_tile128(base + SM_B, B, n0, ldb, k0, tid);
        CP_COMMIT;
    }

    for (int t = 0; t < nt; t++) {
        if (t + 1 < nt) {
            uint32_t base = sb + ((t + 1) & 1) * STAGE_B;
            int kt = k0 + (t + 1) * 32;
            cp_tile128(base + SM_A, A, m0, lda, kt, tid);
            cp_tile128(base + SM_B, B, n0, ldb, kt, tid);
            CP_COMMIT;
            CP_WAIT(1);
        } else {
            CP_WAIT(0);
        }
        __syncthreads();

        uint32_t base = sb + (t & 1) * STAGE_B;
        #pragma unroll
        for (int kk = 0; kk < 32; kk += 16) {
            uint32_t ah[4][4];
            #pragma unroll
            for (int mt = 0; mt < 4; mt++) {
                int row = wm * 64 + mt * 16 + (lane & 15);
                uint32_t off = row * AS_STRIDE_B + (kk + (lane >> 4) * 8) * 2;
                ldsm_x4(ah[mt], base + SM_A + off);
            }
            #pragma unroll
            for (int ng = 0; ng < 4; ng++) {
                uint32_t bh[4];
                int nrow = wn * 64 + ng * 16 + ((lane >> 4) << 3) + (lane & 7);
                uint32_t off = nrow * AS_STRIDE_B + (kk + ((lane >> 3) & 1) * 8) * 2;
                ldsm_x4(bh, base + SM_B + off);
                #pragma unroll
                for (int mt = 0; mt < 4; mt++) {
                    #pragma unroll
                    for (int half = 0; half < 2; half++) {
                        mma_fp16(acc[mt][ng * 2 + half], ah[mt], bh + half * 2);
                    }
                }
            }
        }
        __syncthreads();
    }

    // epilogue: write fp32 partials
    float* C = Cpart + ((size_t)z * BATCH + m0) * N + n0;
    #pragma unroll
    for (int mt = 0; mt < 4; mt++) {
        int r0 = wm * 64 + mt * 16 + (lane >> 2);
        #pragma unroll
        for (int j = 0; j < 8; j++) {
            int col = wn * 64 + j * 8 + (lane & 3) * 2;
            float* c = acc[mt][j];
            *(float2*)(C + (size_t)r0 * N + col)       = make_float2(c[0], c[1]);
            *(float2*)(C + (size_t)(r0 + 8) * N + col) = make_float2(c[2], c[3]);
        }
    }
}

// ---------------- fused: reduce GEMM1 partials + b1 + relu -> A2[:,0:1024)
//                  AND l_out = relu(l @ W2 + b2) -> A2[:,1024:2048), fp16 ----------------
__global__ void reduce1_lout_kernel(const float* __restrict__ part,
                                    const float* __restrict__ b1,
                                    const float* __restrict__ l,
                                    const float* __restrict__ W2,
                                    const float* __restrict__ b2,
                                    __half* __restrict__ A2) {
    int idx = blockIdx.x * blockDim.x + threadIdx.x;   // 0 .. 256*2048-1
    int j = idx & (HOUT - 1);
    int b = idx >> 11;
    float s;
    if (j < HG) {
        s = b1[j];
        int pidx = b * HG + j;
        #pragma unroll
        for (int z = 0; z < SPLITK1; z++)
            s += part[(size_t)z * BATCH * HG + pidx];
    } else {
        int jl = j - HG;
        s = fmaf(l[b * 2 + 0], W2[jl], fmaf(l[b * 2 + 1], W2[HL + jl], b2[jl]));
    }
    s = fmaxf(s, 0.0f);
    A2[idx] = __float2half_rn(s);
}

// ---------------- reduce GEMM2 partials + b3 + b4 + relu -> out ----------------
__global__ void reduce2_kernel(const float* __restrict__ part,
                               const float* __restrict__ b3,
                               const float* __restrict__ b4,
                               float* __restrict__ out) {
    int idx = blockIdx.x * blockDim.x + threadIdx.x;   // 0 .. 256*2048-1
    int j = idx & (HOUT - 1);
    float s = b3[j] + b4[j];
    #pragma unroll
    for (int z = 0; z < SPLITK2; z++)
        s += part[(size_t)z * BATCH * HOUT + idx];
    out[idx] = fmaxf(s, 0.0f);
}

// ---------------- launch ----------------
extern "C" void kernel_launch(void* const* d_in, const int* in_sizes, int n_in,
                              void* d_out, int out_size) {
    const float* x     = (const float*)d_in[0];
    const float* lprev = (const float*)d_in[1];
    const float* W1    = (const float*)d_in[2];
    const float* b1    = (const float*)d_in[3];
    const float* W2    = (const float*)d_in[4];
    const float* b2    = (const float*)d_in[5];
    const float* W3    = (const float*)d_in[6];
    const float* b3    = (const float*)d_in[7];
    const float* W4    = (const float*)d_in[8];
    const float* b4    = (const float*)d_in[9];
    float* out = (float*)d_out;

    __half *A1, *W1h, *B2, *A2;
    float *part1, *part2;
    cudaGetSymbolAddress((void**)&A1,  g_A1);
    cudaGetSymbolAddress((void**)&W1h, g_W1);
    cudaGetSymbolAddress((void**)&B2,  g_B2);
    cudaGetSymbolAddress((void**)&A2,  g_A2);
    cudaGetSymbolAddress((void**)&part1, g_part1);
    cudaGetSymbolAddress((void**)&part2, g_part2);

    cudaFuncSetAttribute(hmma_gemm_kernel,
                         cudaFuncAttributeMaxDynamicSharedMemorySize, GEMM_SMEM);

    // 1. fused prep: foveate + W1 conversion + [W3;W4] conversion
    prep_kernel<<<NB_FOV + NB_W1 + NB_B2, 256>>>(x, lprev, W1, W3, W4, A1, W1h, B2);

    // 2. GEMM1: (256x9216) @ (9216x1024), split-K=18 -> 288 CTAs (2 CTAs/SM)
    hmma_gemm_kernel<<<dim3(HG / 128, BATCH / 128, SPLITK1), 128, GEMM_SMEM>>>(
        A1, DIMG, W1h, DIMG, part1, HG, KCHUNK1);

    // 3. fused reduce + b1 + relu (left) and l_out (right) -> A2 fp16
    reduce1_lout_kernel<<<(BATCH * HOUT) / 256, 256>>>(part1, b1, lprev, W2, b2, A2);

    // 4. GEMM2: (256x2048) @ (2048x2048), split-K=8 -> 256 CTAs
    hmma_gemm_kernel<<<dim3(HOUT / 128, BATCH / 128, SPLITK2), 128, GEMM_SMEM>>>(
        A2, HOUT, B2, HOUT, part2, HOUT, KCHUNK2);

    // 5. reduce + b3 + b4 + relu -> out
    reduce2_kernel<<<(BATCH * HOUT) / 256, 256>>>(part2, b3, b4, out);
}